// round 1
// baseline (speedup 1.0000x reference)
#include <cuda_runtime.h>
#include <math.h>

// Problem constants
#define BB 8
#define NN 89
#define CC 1024
#define HH 512
#define M_EDGE (BB*NN*NN)   // 63368 edge-rows

// Scratch (device globals are the allowed scratch mechanism)
__device__ float g_h1[(size_t)M_EDGE * CC];   // ~260 MB
__device__ float g_h2[(size_t)M_EDGE * HH];   // ~130 MB
__device__ float g_s [M_EDGE];
__device__ float g_at[BB*NN*CC];
__device__ float g_mt[BB*NN*CC];
__device__ float g_t1a[BB*NN*CC];
__device__ float g_t1m[BB*NN*CC];

// ---------------------------------------------------------------------------
// Generic tiled SGEMM:  C = epilogue(A @ B + bias)
//   A: [M, K] row-major (or generated on-the-fly as x_j ⊙ x_i when GEN_A)
//   B: [K, Ncols] row-major
//   mode 0: relu(acc + bias)
//   mode 1: aux + acc + bias              (aux = x, write d_out)
//   mode 2: (aux + acc + bias) / 3        (aux = d_out, RMW d_out)
// BM=BN=128, BK=8, TM=TN=8, 256 threads.
// ---------------------------------------------------------------------------
template<bool GEN_A>
__global__ void __launch_bounds__(256) sgemm_kernel(
    const float* __restrict__ A,
    const float* __restrict__ x,
    const float* __restrict__ Bm,
    const float* __restrict__ bias,
    float* __restrict__ Cmat,
    const float* __restrict__ aux,
    int M, int K, int Ncols, int mode)
{
    const int BM = 128, BN = 128, BK = 8;
    __shared__ float As[BK][BM];
    __shared__ float Bs[BK][BN];

    const int t  = threadIdx.x;
    const int tx = t & 15;        // 0..15 -> 8 cols each
    const int ty = t >> 4;        // 0..15 -> 8 rows each
    const int mBase = blockIdx.y * BM;
    const int nBase = blockIdx.x * BN;

    // A tile loader mapping: one float4 per thread
    const int aRow = t >> 1;          // 0..127
    const int aCol = (t & 1) * 4;     // 0 or 4
    // B tile loader mapping: one float4 per thread
    const int bRow = t >> 5;          // 0..7
    const int bCol = (t & 31) * 4;    // 0..124

    const int row = mBase + aRow;
    const float* xj = nullptr;
    const float* xi = nullptr;
    if (GEN_A) {
        if (row < M) {
            int b   = row / (NN*NN);
            int rem = row - b*(NN*NN);
            int j   = rem / NN;
            int i   = rem - j*NN;
            xj = x + (size_t)(b*NN + j) * CC;
            xi = x + (size_t)(b*NN + i) * CC;
        }
    }

    float acc[8][8];
    #pragma unroll
    for (int m = 0; m < 8; m++)
        #pragma unroll
        for (int n = 0; n < 8; n++) acc[m][n] = 0.f;

    for (int k0 = 0; k0 < K; k0 += BK) {
        float4 av;
        if (row < M) {
            if (GEN_A) {
                float4 vj = *(const float4*)(xj + k0 + aCol);
                float4 vi = *(const float4*)(xi + k0 + aCol);
                av = make_float4(vj.x*vi.x, vj.y*vi.y, vj.z*vi.z, vj.w*vi.w);
            } else {
                av = *(const float4*)(A + (size_t)row * K + k0 + aCol);
            }
        } else {
            av = make_float4(0.f, 0.f, 0.f, 0.f);
        }
        As[aCol+0][aRow] = av.x;
        As[aCol+1][aRow] = av.y;
        As[aCol+2][aRow] = av.z;
        As[aCol+3][aRow] = av.w;

        float4 bv = *(const float4*)(Bm + (size_t)(k0 + bRow) * Ncols + nBase + bCol);
        *(float4*)&Bs[bRow][bCol] = bv;

        __syncthreads();
        #pragma unroll
        for (int kk = 0; kk < BK; kk++) {
            float am[8], bn[8];
            *(float4*)&am[0] = *(const float4*)&As[kk][ty*8];
            *(float4*)&am[4] = *(const float4*)&As[kk][ty*8+4];
            *(float4*)&bn[0] = *(const float4*)&Bs[kk][tx*8];
            *(float4*)&bn[4] = *(const float4*)&Bs[kk][tx*8+4];
            #pragma unroll
            for (int m = 0; m < 8; m++)
                #pragma unroll
                for (int n = 0; n < 8; n++)
                    acc[m][n] = fmaf(am[m], bn[n], acc[m][n]);
        }
        __syncthreads();
    }

    // Epilogue
    #pragma unroll
    for (int m = 0; m < 8; m++) {
        int r = mBase + ty*8 + m;
        if (r >= M) continue;
        #pragma unroll
        for (int n0 = 0; n0 < 8; n0 += 4) {
            int c = nBase + tx*8 + n0;
            float4 bs = *(const float4*)(bias + c);
            float z0 = acc[m][n0+0] + bs.x;
            float z1 = acc[m][n0+1] + bs.y;
            float z2 = acc[m][n0+2] + bs.z;
            float z3 = acc[m][n0+3] + bs.w;
            if (mode == 0) {
                z0 = fmaxf(z0, 0.f); z1 = fmaxf(z1, 0.f);
                z2 = fmaxf(z2, 0.f); z3 = fmaxf(z3, 0.f);
            } else {
                float4 a = *(const float4*)(aux + (size_t)r * Ncols + c);
                z0 += a.x; z1 += a.y; z2 += a.z; z3 += a.w;
                if (mode == 2) {
                    const float k = 1.f/3.f;
                    z0 *= k; z1 *= k; z2 *= k; z3 *= k;
                }
            }
            *(float4*)(Cmat + (size_t)r * Ncols + c) = make_float4(z0, z1, z2, z3);
        }
    }
}

// ---------------------------------------------------------------------------
// s[row] = sigmoid( dot(h2[row, :512], Wa3) + ba3 )   — one warp per row
// ---------------------------------------------------------------------------
__global__ void s_kernel(const float* __restrict__ h2,
                         const float* __restrict__ Wa3,
                         const float* __restrict__ ba3,
                         float* __restrict__ s, int M)
{
    int warp = (blockIdx.x * blockDim.x + threadIdx.x) >> 5;
    int lane = threadIdx.x & 31;
    if (warp >= M) return;
    const float* rowp = h2 + (size_t)warp * HH;
    float acc = 0.f;
    #pragma unroll
    for (int q = 0; q < 4; q++) {
        int k = (lane + q*32) * 4;
        float4 hv = *(const float4*)(rowp + k);
        float4 wv = *(const float4*)(Wa3 + k);
        acc += hv.x*wv.x + hv.y*wv.y + hv.z*wv.z + hv.w*wv.w;
    }
    #pragma unroll
    for (int o = 16; o > 0; o >>= 1)
        acc += __shfl_xor_sync(0xffffffffu, acc, o);
    if (lane == 0)
        s[warp] = 1.f / (1.f + expf(-(acc + ba3[0])));
}

// ---------------------------------------------------------------------------
// Graph aggregation:
//   at[b,i,f] = sum_j s[b,j,i] * adj_add[j,i] * x[b,j,f]
//   mt[b,i,f] = x[b,i,f] * sum_j adj_mod[j,i] * x[b,j,f]
// one block per (b, i); 256 threads x float4 over f
// ---------------------------------------------------------------------------
__global__ void __launch_bounds__(256) agg_kernel(
    const float* __restrict__ x,
    const float* __restrict__ s,
    const float* __restrict__ adj_add,
    const float* __restrict__ adj_mod,
    float* __restrict__ at, float* __restrict__ mt)
{
    int bi = blockIdx.x;          // 0 .. B*N-1
    int b = bi / NN, i = bi - b*NN;
    int f = threadIdx.x * 4;

    float4 aa = make_float4(0,0,0,0);
    float4 mm = make_float4(0,0,0,0);
    for (int j = 0; j < NN; j++) {
        float sv = s[(b*NN + j)*NN + i];
        float wa = sv * adj_add[j*NN + i];
        float wm = adj_mod[j*NN + i];
        float4 xv = *(const float4*)(x + (size_t)(b*NN + j)*CC + f);
        aa.x = fmaf(wa, xv.x, aa.x); aa.y = fmaf(wa, xv.y, aa.y);
        aa.z = fmaf(wa, xv.z, aa.z); aa.w = fmaf(wa, xv.w, aa.w);
        mm.x = fmaf(wm, xv.x, mm.x); mm.y = fmaf(wm, xv.y, mm.y);
        mm.z = fmaf(wm, xv.z, mm.z); mm.w = fmaf(wm, xv.w, mm.w);
    }
    float4 xv = *(const float4*)(x + (size_t)bi * CC + f);
    mm.x *= xv.x; mm.y *= xv.y; mm.z *= xv.z; mm.w *= xv.w;
    *(float4*)(at + (size_t)bi * CC + f) = aa;
    *(float4*)(mt + (size_t)bi * CC + f) = mm;
}

// ---------------------------------------------------------------------------
extern "C" void kernel_launch(void* const* d_in, const int* in_sizes, int n_in,
                              void* d_out, int out_size)
{
    const float* x       = (const float*)d_in[0];
    const float* adj_add = (const float*)d_in[1];
    const float* adj_mod = (const float*)d_in[2];
    const float* Wa1  = (const float*)d_in[3];
    const float* ba1  = (const float*)d_in[4];
    const float* Wa2  = (const float*)d_in[5];
    const float* ba2  = (const float*)d_in[6];
    const float* Wa3  = (const float*)d_in[7];
    const float* ba3  = (const float*)d_in[8];
    const float* Wadd1 = (const float*)d_in[9];
    const float* badd1 = (const float*)d_in[10];
    const float* Wadd2 = (const float*)d_in[11];
    const float* badd2 = (const float*)d_in[12];
    const float* Wmod1 = (const float*)d_in[13];
    const float* bmod1 = (const float*)d_in[14];
    const float* Wmod2 = (const float*)d_in[15];
    const float* Wbmod2= (const float*)d_in[16];
    float* out = (float*)d_out;

    float *h1, *h2, *sptr, *at, *mt, *t1a, *t1m;
    cudaGetSymbolAddress((void**)&h1,  g_h1);
    cudaGetSymbolAddress((void**)&h2,  g_h2);
    cudaGetSymbolAddress((void**)&sptr,g_s);
    cudaGetSymbolAddress((void**)&at,  g_at);
    cudaGetSymbolAddress((void**)&mt,  g_mt);
    cudaGetSymbolAddress((void**)&t1a, g_t1a);
    cudaGetSymbolAddress((void**)&t1m, g_t1m);

    const int M = M_EDGE;                 // 63368
    const int MT = (M + 127) / 128;       // 496
    const int MR = BB * NN;               // 712
    const int MRT = (MR + 127) / 128;     // 6

    // 1) h1 = relu((x_j ⊙ x_i) @ Wa1 + ba1)     [M,1024]
    sgemm_kernel<true><<<dim3(CC/128, MT), 256>>>(
        nullptr, x, Wa1, ba1, h1, nullptr, M, CC, CC, 0);

    // 2) h2 = relu(h1 @ Wa2 + ba2)              [M,512]
    sgemm_kernel<false><<<dim3(HH/128, MT), 256>>>(
        h1, nullptr, Wa2, ba2, h2, nullptr, M, CC, HH, 0);

    // 3) s = sigmoid(h2 @ Wa3 + ba3)            [M]
    s_kernel<<<(M*32 + 255)/256, 256>>>(h2, Wa3, ba3, sptr, M);

    // 4) graph aggregation -> at, mt            [B*N,1024]
    agg_kernel<<<MR, 256>>>(x, sptr, adj_add, adj_mod, at, mt);

    // 5) first layers of output MLPs
    sgemm_kernel<false><<<dim3(CC/128, MRT), 256>>>(
        at, nullptr, Wadd1, badd1, t1a, nullptr, MR, CC, CC, 0);
    sgemm_kernel<false><<<dim3(CC/128, MRT), 256>>>(
        mt, nullptr, Wmod1, bmod1, t1m, nullptr, MR, CC, CC, 0);

    // 6) out = x + (t1a @ Wadd2 + badd2)
    sgemm_kernel<false><<<dim3(CC/128, MRT), 256>>>(
        t1a, nullptr, Wadd2, badd2, out, x, MR, CC, CC, 1);

    // 7) out = (out + (t1m @ Wmod2 + bmod2)) / 3
    sgemm_kernel<false><<<dim3(CC/128, MRT), 256>>>(
        t1m, nullptr, Wmod2, Wbmod2, out, out, MR, CC, CC, 2);
}

// round 2
// speedup vs baseline: 2.7493x; 2.7493x over previous
#include <cuda_runtime.h>
#include <math.h>

// Problem constants
#define BB 8
#define NN 89
#define CC 1024
#define HH 512
#define M_EDGE (BB*NN*NN)   // 63368 edge-rows

// Scratch (device globals)
__device__ float g_h1[(size_t)M_EDGE * CC];   // ~260 MB
__device__ float g_h2[(size_t)M_EDGE * HH];   // ~130 MB
__device__ float g_s [M_EDGE];
__device__ float g_at[BB*NN*CC];
__device__ float g_mt[BB*NN*CC];
__device__ float g_t1a[BB*NN*CC];
__device__ float g_t1m[BB*NN*CC];

// ---------------------------------------------------------------------------
// TF32 helpers
// ---------------------------------------------------------------------------
__device__ __forceinline__ unsigned f2tf32(float x){
    unsigned r; asm("cvt.rna.tf32.f32 %0, %1;" : "=r"(r) : "f"(x)); return r;
}
__device__ __forceinline__ float4 cvt4(float4 v){
    return make_float4(__uint_as_float(f2tf32(v.x)), __uint_as_float(f2tf32(v.y)),
                       __uint_as_float(f2tf32(v.z)), __uint_as_float(f2tf32(v.w)));
}
__device__ __forceinline__ void mma_tf32(float c[4], const unsigned a[4], const unsigned b[2]){
    asm volatile("mma.sync.aligned.m16n8k8.row.col.f32.tf32.tf32.f32 "
        "{%0,%1,%2,%3}, {%4,%5,%6,%7}, {%8,%9}, {%0,%1,%2,%3};\n"
        : "+f"(c[0]), "+f"(c[1]), "+f"(c[2]), "+f"(c[3])
        : "r"(a[0]), "r"(a[1]), "r"(a[2]), "r"(a[3]), "r"(b[0]), "r"(b[1]));
}

// ---------------------------------------------------------------------------
// TF32 tensor-core GEMM:  C = epilogue(A @ B + bias)
//   A: [M,K] row-major (or generated on the fly as x_j ⊙ x_i when GEN_A)
//   B: [K,Ncols] row-major
//   mode 0: relu(acc+bias)   mode 1: aux+acc+bias   mode 2: (aux+acc+bias)/3
// BM=BN=128, BK=16, 256 threads (8 warps as 2x4, warp tile 64x32).
// ---------------------------------------------------------------------------
#define BM 128
#define BN 128
#define BKT 16
#define PADA 8
#define PADB 8

template<bool GEN_A>
__global__ void __launch_bounds__(256) mma_gemm(
    const float* __restrict__ A, const float* __restrict__ x,
    const float* __restrict__ Bm, const float* __restrict__ bias,
    float* __restrict__ Cmat, const float* __restrict__ aux,
    int M, int K, int Ncols, int mode)
{
    __shared__ __align__(16) float As[2][BKT][BM+PADA];
    __shared__ __align__(16) float Bs[2][BKT][BN+PADB];

    const int t    = threadIdx.x;
    const int warp = t >> 5, lane = t & 31;
    const int g    = lane >> 2, tig = lane & 3;
    const int wm   = (warp >> 2) * 64;      // warp row offset in tile
    const int wn   = (warp & 3) * 32;       // warp col offset in tile
    const int mBase = blockIdx.y * BM;
    const int nBase = blockIdx.x * BN;

    // -------- global A loader: thread covers rows (arow, arow+64), 4 k-floats
    const int arow = t >> 2;                // 0..63
    const int akq  = (t & 3) * 4;           // 0,4,8,12
    const int grow0 = mBase + arow;
    const int grow1 = mBase + arow + 64;
    const bool v0 = grow0 < M, v1 = grow1 < M;
    const float *ap0=nullptr, *ap1=nullptr;
    const float *xj0=nullptr, *xi0=nullptr, *xj1=nullptr, *xi1=nullptr;
    if (GEN_A) {
        if (v0){ int b=grow0/(NN*NN), r=grow0-b*(NN*NN), j=r/NN, i=r-j*NN;
                 xj0 = x + (size_t)(b*NN+j)*CC; xi0 = x + (size_t)(b*NN+i)*CC; }
        if (v1){ int b=grow1/(NN*NN), r=grow1-b*(NN*NN), j=r/NN, i=r-j*NN;
                 xj1 = x + (size_t)(b*NN+j)*CC; xi1 = x + (size_t)(b*NN+i)*CC; }
    } else {
        if (v0) ap0 = A + (size_t)grow0 * K;
        if (v1) ap1 = A + (size_t)grow1 * K;
    }
    // -------- global B loader: rows (bkr, bkr+8), 4 n-floats
    const int bkr = t >> 5;                 // 0..7
    const int bnc = (t & 31) * 4;

    float4 a0s, a1s, b0s, b1s;

    auto load_g = [&](int k0){
        const float4 z = make_float4(0,0,0,0);
        if (GEN_A) {
            if (v0){ float4 j4 = *(const float4*)(xj0 + k0 + akq);
                     float4 i4 = *(const float4*)(xi0 + k0 + akq);
                     a0s = make_float4(j4.x*i4.x, j4.y*i4.y, j4.z*i4.z, j4.w*i4.w); }
            else a0s = z;
            if (v1){ float4 j4 = *(const float4*)(xj1 + k0 + akq);
                     float4 i4 = *(const float4*)(xi1 + k0 + akq);
                     a1s = make_float4(j4.x*i4.x, j4.y*i4.y, j4.z*i4.z, j4.w*i4.w); }
            else a1s = z;
        } else {
            a0s = v0 ? *(const float4*)(ap0 + k0 + akq) : z;
            a1s = v1 ? *(const float4*)(ap1 + k0 + akq) : z;
        }
        b0s = *(const float4*)(Bm + (size_t)(k0 + bkr    ) * Ncols + nBase + bnc);
        b1s = *(const float4*)(Bm + (size_t)(k0 + bkr + 8) * Ncols + nBase + bnc);
    };
    auto store_s = [&](int buf){
        float4 ac0 = cvt4(a0s), ac1 = cvt4(a1s);
        As[buf][akq+0][arow]    = ac0.x;
        As[buf][akq+1][arow]    = ac0.y;
        As[buf][akq+2][arow]    = ac0.z;
        As[buf][akq+3][arow]    = ac0.w;
        As[buf][akq+0][arow+64] = ac1.x;
        As[buf][akq+1][arow+64] = ac1.y;
        As[buf][akq+2][arow+64] = ac1.z;
        As[buf][akq+3][arow+64] = ac1.w;
        *(float4*)&Bs[buf][bkr    ][bnc] = cvt4(b0s);
        *(float4*)&Bs[buf][bkr + 8][bnc] = cvt4(b1s);
    };

    float acc[4][4][4];
    #pragma unroll
    for (int mi = 0; mi < 4; mi++)
        #pragma unroll
        for (int ni = 0; ni < 4; ni++)
            #pragma unroll
            for (int q = 0; q < 4; q++) acc[mi][ni][q] = 0.f;

    load_g(0);
    store_s(0);
    __syncthreads();

    const int KT = K / BKT;
    for (int kt = 0; kt < KT; kt++) {
        const int cur = kt & 1;
        if (kt + 1 < KT) load_g((kt + 1) * BKT);

        #pragma unroll
        for (int ko = 0; ko < BKT; ko += 8) {
            unsigned af[4][4], bf[4][2];
            #pragma unroll
            for (int mi = 0; mi < 4; mi++) {
                const int m0 = wm + mi*16 + g;
                af[mi][0] = __float_as_uint(As[cur][ko + tig    ][m0    ]);
                af[mi][1] = __float_as_uint(As[cur][ko + tig    ][m0 + 8]);
                af[mi][2] = __float_as_uint(As[cur][ko + tig + 4][m0    ]);
                af[mi][3] = __float_as_uint(As[cur][ko + tig + 4][m0 + 8]);
            }
            #pragma unroll
            for (int ni = 0; ni < 4; ni++) {
                const int n0 = wn + ni*8 + g;
                bf[ni][0] = __float_as_uint(Bs[cur][ko + tig    ][n0]);
                bf[ni][1] = __float_as_uint(Bs[cur][ko + tig + 4][n0]);
            }
            #pragma unroll
            for (int mi = 0; mi < 4; mi++)
                #pragma unroll
                for (int ni = 0; ni < 4; ni++)
                    mma_tf32(acc[mi][ni], af[mi], bf[ni]);
        }

        if (kt + 1 < KT) store_s((kt + 1) & 1);
        __syncthreads();
    }

    // -------- epilogue (float2 stores; c0,c1 are adjacent columns) --------
    #pragma unroll
    for (int mi = 0; mi < 4; mi++) {
        #pragma unroll
        for (int ni = 0; ni < 4; ni++) {
            const int cb = nBase + wn + ni*8 + 2*tig;
            const float2 bs = *(const float2*)(bias + cb);
            #pragma unroll
            for (int half = 0; half < 2; half++) {
                const int r = mBase + wm + mi*16 + g + half*8;
                if (r >= M) continue;
                float z0 = acc[mi][ni][half*2+0] + bs.x;
                float z1 = acc[mi][ni][half*2+1] + bs.y;
                if (mode == 0) {
                    z0 = fmaxf(z0, 0.f); z1 = fmaxf(z1, 0.f);
                } else {
                    const float2 a = *(const float2*)(aux + (size_t)r * Ncols + cb);
                    z0 += a.x; z1 += a.y;
                    if (mode == 2) { z0 *= (1.f/3.f); z1 *= (1.f/3.f); }
                }
                *(float2*)(Cmat + (size_t)r * Ncols + cb) = make_float2(z0, z1);
            }
        }
    }
}

// ---------------------------------------------------------------------------
// s[row] = sigmoid( dot(h2[row,:512], Wa3) + ba3 )  — one warp per row
// ---------------------------------------------------------------------------
__global__ void s_kernel(const float* __restrict__ h2,
                         const float* __restrict__ Wa3,
                         const float* __restrict__ ba3,
                         float* __restrict__ s, int M)
{
    int warp = (blockIdx.x * blockDim.x + threadIdx.x) >> 5;
    int lane = threadIdx.x & 31;
    if (warp >= M) return;
    const float* rowp = h2 + (size_t)warp * HH;
    float acc = 0.f;
    #pragma unroll
    for (int q = 0; q < 4; q++) {
        int k = (lane + q*32) * 4;
        float4 hv = *(const float4*)(rowp + k);
        float4 wv = *(const float4*)(Wa3 + k);
        acc += hv.x*wv.x + hv.y*wv.y + hv.z*wv.z + hv.w*wv.w;
    }
    #pragma unroll
    for (int o = 16; o > 0; o >>= 1)
        acc += __shfl_xor_sync(0xffffffffu, acc, o);
    if (lane == 0)
        s[warp] = 1.f / (1.f + expf(-(acc + ba3[0])));
}

// ---------------------------------------------------------------------------
// Graph aggregation
// ---------------------------------------------------------------------------
__global__ void __launch_bounds__(256) agg_kernel(
    const float* __restrict__ x,
    const float* __restrict__ s,
    const float* __restrict__ adj_add,
    const float* __restrict__ adj_mod,
    float* __restrict__ at, float* __restrict__ mt)
{
    int bi = blockIdx.x;          // 0 .. B*N-1
    int b = bi / NN, i = bi - b*NN;
    int f = threadIdx.x * 4;

    float4 aa = make_float4(0,0,0,0);
    float4 mm = make_float4(0,0,0,0);
    for (int j = 0; j < NN; j++) {
        float sv = s[(b*NN + j)*NN + i];
        float wa = sv * adj_add[j*NN + i];
        float wm = adj_mod[j*NN + i];
        float4 xv = *(const float4*)(x + (size_t)(b*NN + j)*CC + f);
        aa.x = fmaf(wa, xv.x, aa.x); aa.y = fmaf(wa, xv.y, aa.y);
        aa.z = fmaf(wa, xv.z, aa.z); aa.w = fmaf(wa, xv.w, aa.w);
        mm.x = fmaf(wm, xv.x, mm.x); mm.y = fmaf(wm, xv.y, mm.y);
        mm.z = fmaf(wm, xv.z, mm.z); mm.w = fmaf(wm, xv.w, mm.w);
    }
    float4 xv = *(const float4*)(x + (size_t)bi * CC + f);
    mm.x *= xv.x; mm.y *= xv.y; mm.z *= xv.z; mm.w *= xv.w;
    *(float4*)(at + (size_t)bi * CC + f) = aa;
    *(float4*)(mt + (size_t)bi * CC + f) = mm;
}

// ---------------------------------------------------------------------------
extern "C" void kernel_launch(void* const* d_in, const int* in_sizes, int n_in,
                              void* d_out, int out_size)
{
    const float* x       = (const float*)d_in[0];
    const float* adj_add = (const float*)d_in[1];
    const float* adj_mod = (const float*)d_in[2];
    const float* Wa1  = (const float*)d_in[3];
    const float* ba1  = (const float*)d_in[4];
    const float* Wa2  = (const float*)d_in[5];
    const float* ba2  = (const float*)d_in[6];
    const float* Wa3  = (const float*)d_in[7];
    const float* ba3  = (const float*)d_in[8];
    const float* Wadd1 = (const float*)d_in[9];
    const float* badd1 = (const float*)d_in[10];
    const float* Wadd2 = (const float*)d_in[11];
    const float* badd2 = (const float*)d_in[12];
    const float* Wmod1 = (const float*)d_in[13];
    const float* bmod1 = (const float*)d_in[14];
    const float* Wmod2 = (const float*)d_in[15];
    const float* bmod2 = (const float*)d_in[16];
    float* out = (float*)d_out;

    float *h1, *h2, *sptr, *at, *mt, *t1a, *t1m;
    cudaGetSymbolAddress((void**)&h1,  g_h1);
    cudaGetSymbolAddress((void**)&h2,  g_h2);
    cudaGetSymbolAddress((void**)&sptr,g_s);
    cudaGetSymbolAddress((void**)&at,  g_at);
    cudaGetSymbolAddress((void**)&mt,  g_mt);
    cudaGetSymbolAddress((void**)&t1a, g_t1a);
    cudaGetSymbolAddress((void**)&t1m, g_t1m);

    const int M   = M_EDGE;               // 63368
    const int MT  = (M + BM - 1) / BM;    // 496
    const int MR  = BB * NN;              // 712
    const int MRT = (MR + BM - 1) / BM;   // 6

    // 1) h1 = relu((x_j ⊙ x_i) @ Wa1 + ba1)     [M,1024]
    mma_gemm<true><<<dim3(CC/BN, MT), 256>>>(
        nullptr, x, Wa1, ba1, h1, nullptr, M, CC, CC, 0);

    // 2) h2 = relu(h1 @ Wa2 + ba2)              [M,512]
    mma_gemm<false><<<dim3(HH/BN, MT), 256>>>(
        h1, nullptr, Wa2, ba2, h2, nullptr, M, CC, HH, 0);

    // 3) s = sigmoid(h2 @ Wa3 + ba3)            [M]
    s_kernel<<<(M*32 + 255)/256, 256>>>(h2, Wa3, ba3, sptr, M);

    // 4) graph aggregation -> at, mt            [B*N,1024]
    agg_kernel<<<MR, 256>>>(x, sptr, adj_add, adj_mod, at, mt);

    // 5) first layers of output MLPs
    mma_gemm<false><<<dim3(CC/BN, MRT), 256>>>(
        at, nullptr, Wadd1, badd1, t1a, nullptr, MR, CC, CC, 0);
    mma_gemm<false><<<dim3(CC/BN, MRT), 256>>>(
        mt, nullptr, Wmod1, bmod1, t1m, nullptr, MR, CC, CC, 0);

    // 6) out = x + (t1a @ Wadd2 + badd2)
    mma_gemm<false><<<dim3(CC/BN, MRT), 256>>>(
        t1a, nullptr, Wadd2, badd2, out, x, MR, CC, CC, 1);

    // 7) out = (out + (t1m @ Wmod2 + bmod2)) / 3
    mma_gemm<false><<<dim3(CC/BN, MRT), 256>>>(
        t1m, nullptr, Wmod2, bmod2, out, out, MR, CC, CC, 2);
}

// round 3
// speedup vs baseline: 2.7494x; 1.0000x over previous
#include <cuda_runtime.h>
#include <math.h>

// Problem constants
#define BB 8
#define NN 89
#define CC 1024
#define HH 512
#define M_EDGE (BB*NN*NN)   // 63368 edge-rows

// Scratch (device globals)
__device__ float g_h1[(size_t)M_EDGE * CC];   // ~260 MB
__device__ float g_h2[(size_t)M_EDGE * HH];   // ~130 MB
__device__ float g_s [M_EDGE];
__device__ float g_at[BB*NN*CC];
__device__ float g_mt[BB*NN*CC];
__device__ float g_t1a[BB*NN*CC];
__device__ float g_t1m[BB*NN*CC];

// ---------------------------------------------------------------------------
// TF32 helpers
// ---------------------------------------------------------------------------
__device__ __forceinline__ unsigned f2tf32(float x){
    unsigned r; asm("cvt.rna.tf32.f32 %0, %1;" : "=r"(r) : "f"(x)); return r;
}
__device__ __forceinline__ float4 cvt4(float4 v){
    return make_float4(__uint_as_float(f2tf32(v.x)), __uint_as_float(f2tf32(v.y)),
                       __uint_as_float(f2tf32(v.z)), __uint_as_float(f2tf32(v.w)));
}
__device__ __forceinline__ void mma_tf32(float c[4], const unsigned a[4], const unsigned b[2]){
    asm volatile("mma.sync.aligned.m16n8k8.row.col.f32.tf32.tf32.f32 "
        "{%0,%1,%2,%3}, {%4,%5,%6,%7}, {%8,%9}, {%0,%1,%2,%3};\n"
        : "+f"(c[0]), "+f"(c[1]), "+f"(c[2]), "+f"(c[3])
        : "r"(a[0]), "r"(a[1]), "r"(a[2]), "r"(a[3]), "r"(b[0]), "r"(b[1]));
}

// ---------------------------------------------------------------------------
// TF32 tensor-core GEMM:  C = epilogue(A @ B + bias)
//   A: [M,K] row-major (or generated on the fly as x_j ⊙ x_i when GEN_A)
//   B: [K,Ncols] row-major
//   mode 0: relu(acc+bias)   mode 1: aux+acc+bias   mode 2: (aux+acc+bias)/3
// BM=BN=128, BK=16, 256 threads (8 warps as 2x4, warp tile 64x32).
// ---------------------------------------------------------------------------
#define BM 128
#define BN 128
#define BKT 16
#define PADA 8
#define PADB 8

template<bool GEN_A>
__global__ void __launch_bounds__(256) mma_gemm(
    const float* __restrict__ A, const float* __restrict__ x,
    const float* __restrict__ Bm, const float* __restrict__ bias,
    float* __restrict__ Cmat, const float* __restrict__ aux,
    int M, int K, int Ncols, int mode)
{
    __shared__ __align__(16) float As[2][BKT][BM+PADA];
    __shared__ __align__(16) float Bs[2][BKT][BN+PADB];

    const int t    = threadIdx.x;
    const int warp = t >> 5, lane = t & 31;
    const int g    = lane >> 2, tig = lane & 3;
    const int wm   = (warp >> 2) * 64;      // warp row offset in tile
    const int wn   = (warp & 3) * 32;       // warp col offset in tile
    const int mBase = blockIdx.y * BM;
    const int nBase = blockIdx.x * BN;

    // -------- global A loader: thread covers rows (arow, arow+64), 4 k-floats
    const int arow = t >> 2;                // 0..63
    const int akq  = (t & 3) * 4;           // 0,4,8,12
    const int grow0 = mBase + arow;
    const int grow1 = mBase + arow + 64;
    const bool v0 = grow0 < M, v1 = grow1 < M;
    const float *ap0=nullptr, *ap1=nullptr;
    const float *xj0=nullptr, *xi0=nullptr, *xj1=nullptr, *xi1=nullptr;
    if (GEN_A) {
        if (v0){ int b=grow0/(NN*NN), r=grow0-b*(NN*NN), j=r/NN, i=r-j*NN;
                 xj0 = x + (size_t)(b*NN+j)*CC; xi0 = x + (size_t)(b*NN+i)*CC; }
        if (v1){ int b=grow1/(NN*NN), r=grow1-b*(NN*NN), j=r/NN, i=r-j*NN;
                 xj1 = x + (size_t)(b*NN+j)*CC; xi1 = x + (size_t)(b*NN+i)*CC; }
    } else {
        if (v0) ap0 = A + (size_t)grow0 * K;
        if (v1) ap1 = A + (size_t)grow1 * K;
    }
    // -------- global B loader: rows (bkr, bkr+8), 4 n-floats
    const int bkr = t >> 5;                 // 0..7
    const int bnc = (t & 31) * 4;

    float4 a0s, a1s, b0s, b1s;

    auto load_g = [&](int k0){
        const float4 z = make_float4(0,0,0,0);
        if (GEN_A) {
            if (v0){ float4 j4 = *(const float4*)(xj0 + k0 + akq);
                     float4 i4 = *(const float4*)(xi0 + k0 + akq);
                     a0s = make_float4(j4.x*i4.x, j4.y*i4.y, j4.z*i4.z, j4.w*i4.w); }
            else a0s = z;
            if (v1){ float4 j4 = *(const float4*)(xj1 + k0 + akq);
                     float4 i4 = *(const float4*)(xi1 + k0 + akq);
                     a1s = make_float4(j4.x*i4.x, j4.y*i4.y, j4.z*i4.z, j4.w*i4.w); }
            else a1s = z;
        } else {
            a0s = v0 ? *(const float4*)(ap0 + k0 + akq) : z;
            a1s = v1 ? *(const float4*)(ap1 + k0 + akq) : z;
        }
        b0s = *(const float4*)(Bm + (size_t)(k0 + bkr    ) * Ncols + nBase + bnc);
        b1s = *(const float4*)(Bm + (size_t)(k0 + bkr + 8) * Ncols + nBase + bnc);
    };
    auto store_s = [&](int buf){
        float4 ac0 = cvt4(a0s), ac1 = cvt4(a1s);
        As[buf][akq+0][arow]    = ac0.x;
        As[buf][akq+1][arow]    = ac0.y;
        As[buf][akq+2][arow]    = ac0.z;
        As[buf][akq+3][arow]    = ac0.w;
        As[buf][akq+0][arow+64] = ac1.x;
        As[buf][akq+1][arow+64] = ac1.y;
        As[buf][akq+2][arow+64] = ac1.z;
        As[buf][akq+3][arow+64] = ac1.w;
        *(float4*)&Bs[buf][bkr    ][bnc] = cvt4(b0s);
        *(float4*)&Bs[buf][bkr + 8][bnc] = cvt4(b1s);
    };

    float acc[4][4][4];
    #pragma unroll
    for (int mi = 0; mi < 4; mi++)
        #pragma unroll
        for (int ni = 0; ni < 4; ni++)
            #pragma unroll
            for (int q = 0; q < 4; q++) acc[mi][ni][q] = 0.f;

    load_g(0);
    store_s(0);
    __syncthreads();

    const int KT = K / BKT;
    for (int kt = 0; kt < KT; kt++) {
        const int cur = kt & 1;
        if (kt + 1 < KT) load_g((kt + 1) * BKT);

        #pragma unroll
        for (int ko = 0; ko < BKT; ko += 8) {
            unsigned af[4][4], bf[4][2];
            #pragma unroll
            for (int mi = 0; mi < 4; mi++) {
                const int m0 = wm + mi*16 + g;
                af[mi][0] = __float_as_uint(As[cur][ko + tig    ][m0    ]);
                af[mi][1] = __float_as_uint(As[cur][ko + tig    ][m0 + 8]);
                af[mi][2] = __float_as_uint(As[cur][ko + tig + 4][m0    ]);
                af[mi][3] = __float_as_uint(As[cur][ko + tig + 4][m0 + 8]);
            }
            #pragma unroll
            for (int ni = 0; ni < 4; ni++) {
                const int n0 = wn + ni*8 + g;
                bf[ni][0] = __float_as_uint(Bs[cur][ko + tig    ][n0]);
                bf[ni][1] = __float_as_uint(Bs[cur][ko + tig + 4][n0]);
            }
            #pragma unroll
            for (int mi = 0; mi < 4; mi++)
                #pragma unroll
                for (int ni = 0; ni < 4; ni++)
                    mma_tf32(acc[mi][ni], af[mi], bf[ni]);
        }

        if (kt + 1 < KT) store_s((kt + 1) & 1);
        __syncthreads();
    }

    // -------- epilogue (float2 stores; c0,c1 are adjacent columns) --------
    #pragma unroll
    for (int mi = 0; mi < 4; mi++) {
        #pragma unroll
        for (int ni = 0; ni < 4; ni++) {
            const int cb = nBase + wn + ni*8 + 2*tig;
            const float2 bs = *(const float2*)(bias + cb);
            #pragma unroll
            for (int half = 0; half < 2; half++) {
                const int r = mBase + wm + mi*16 + g + half*8;
                if (r >= M) continue;
                float z0 = acc[mi][ni][half*2+0] + bs.x;
                float z1 = acc[mi][ni][half*2+1] + bs.y;
                if (mode == 0) {
                    z0 = fmaxf(z0, 0.f); z1 = fmaxf(z1, 0.f);
                } else {
                    const float2 a = *(const float2*)(aux + (size_t)r * Ncols + cb);
                    z0 += a.x; z1 += a.y;
                    if (mode == 2) { z0 *= (1.f/3.f); z1 *= (1.f/3.f); }
                }
                *(float2*)(Cmat + (size_t)r * Ncols + cb) = make_float2(z0, z1);
            }
        }
    }
}

// ---------------------------------------------------------------------------
// s[row] = sigmoid( dot(h2[row,:512], Wa3) + ba3 )  — one warp per row
// ---------------------------------------------------------------------------
__global__ void s_kernel(const float* __restrict__ h2,
                         const float* __restrict__ Wa3,
                         const float* __restrict__ ba3,
                         float* __restrict__ s, int M)
{
    int warp = (blockIdx.x * blockDim.x + threadIdx.x) >> 5;
    int lane = threadIdx.x & 31;
    if (warp >= M) return;
    const float* rowp = h2 + (size_t)warp * HH;
    float acc = 0.f;
    #pragma unroll
    for (int q = 0; q < 4; q++) {
        int k = (lane + q*32) * 4;
        float4 hv = *(const float4*)(rowp + k);
        float4 wv = *(const float4*)(Wa3 + k);
        acc += hv.x*wv.x + hv.y*wv.y + hv.z*wv.z + hv.w*wv.w;
    }
    #pragma unroll
    for (int o = 16; o > 0; o >>= 1)
        acc += __shfl_xor_sync(0xffffffffu, acc, o);
    if (lane == 0)
        s[warp] = 1.f / (1.f + expf(-(acc + ba3[0])));
}

// ---------------------------------------------------------------------------
// Graph aggregation
// ---------------------------------------------------------------------------
__global__ void __launch_bounds__(256) agg_kernel(
    const float* __restrict__ x,
    const float* __restrict__ s,
    const float* __restrict__ adj_add,
    const float* __restrict__ adj_mod,
    float* __restrict__ at, float* __restrict__ mt)
{
    int bi = blockIdx.x;          // 0 .. B*N-1
    int b = bi / NN, i = bi - b*NN;
    int f = threadIdx.x * 4;

    float4 aa = make_float4(0,0,0,0);
    float4 mm = make_float4(0,0,0,0);
    for (int j = 0; j < NN; j++) {
        float sv = s[(b*NN + j)*NN + i];
        float wa = sv * adj_add[j*NN + i];
        float wm = adj_mod[j*NN + i];
        float4 xv = *(const float4*)(x + (size_t)(b*NN + j)*CC + f);
        aa.x = fmaf(wa, xv.x, aa.x); aa.y = fmaf(wa, xv.y, aa.y);
        aa.z = fmaf(wa, xv.z, aa.z); aa.w = fmaf(wa, xv.w, aa.w);
        mm.x = fmaf(wm, xv.x, mm.x); mm.y = fmaf(wm, xv.y, mm.y);
        mm.z = fmaf(wm, xv.z, mm.z); mm.w = fmaf(wm, xv.w, mm.w);
    }
    float4 xv = *(const float4*)(x + (size_t)bi * CC + f);
    mm.x *= xv.x; mm.y *= xv.y; mm.z *= xv.z; mm.w *= xv.w;
    *(float4*)(at + (size_t)bi * CC + f) = aa;
    *(float4*)(mt + (size_t)bi * CC + f) = mm;
}

// ---------------------------------------------------------------------------
extern "C" void kernel_launch(void* const* d_in, const int* in_sizes, int n_in,
                              void* d_out, int out_size)
{
    const float* x       = (const float*)d_in[0];
    const float* adj_add = (const float*)d_in[1];
    const float* adj_mod = (const float*)d_in[2];
    const float* Wa1  = (const float*)d_in[3];
    const float* ba1  = (const float*)d_in[4];
    const float* Wa2  = (const float*)d_in[5];
    const float* ba2  = (const float*)d_in[6];
    const float* Wa3  = (const float*)d_in[7];
    const float* ba3  = (const float*)d_in[8];
    const float* Wadd1 = (const float*)d_in[9];
    const float* badd1 = (const float*)d_in[10];
    const float* Wadd2 = (const float*)d_in[11];
    const float* badd2 = (const float*)d_in[12];
    const float* Wmod1 = (const float*)d_in[13];
    const float* bmod1 = (const float*)d_in[14];
    const float* Wmod2 = (const float*)d_in[15];
    const float* bmod2 = (const float*)d_in[16];
    float* out = (float*)d_out;

    float *h1, *h2, *sptr, *at, *mt, *t1a, *t1m;
    cudaGetSymbolAddress((void**)&h1,  g_h1);
    cudaGetSymbolAddress((void**)&h2,  g_h2);
    cudaGetSymbolAddress((void**)&sptr,g_s);
    cudaGetSymbolAddress((void**)&at,  g_at);
    cudaGetSymbolAddress((void**)&mt,  g_mt);
    cudaGetSymbolAddress((void**)&t1a, g_t1a);
    cudaGetSymbolAddress((void**)&t1m, g_t1m);

    const int M   = M_EDGE;               // 63368
    const int MT  = (M + BM - 1) / BM;    // 496
    const int MR  = BB * NN;              // 712
    const int MRT = (MR + BM - 1) / BM;   // 6

    // 1) h1 = relu((x_j ⊙ x_i) @ Wa1 + ba1)     [M,1024]
    mma_gemm<true><<<dim3(CC/BN, MT), 256>>>(
        nullptr, x, Wa1, ba1, h1, nullptr, M, CC, CC, 0);

    // 2) h2 = relu(h1 @ Wa2 + ba2)              [M,512]
    mma_gemm<false><<<dim3(HH/BN, MT), 256>>>(
        h1, nullptr, Wa2, ba2, h2, nullptr, M, CC, HH, 0);

    // 3) s = sigmoid(h2 @ Wa3 + ba3)            [M]
    s_kernel<<<(M*32 + 255)/256, 256>>>(h2, Wa3, ba3, sptr, M);

    // 4) graph aggregation -> at, mt            [B*N,1024]
    agg_kernel<<<MR, 256>>>(x, sptr, adj_add, adj_mod, at, mt);

    // 5) first layers of output MLPs
    mma_gemm<false><<<dim3(CC/BN, MRT), 256>>>(
        at, nullptr, Wadd1, badd1, t1a, nullptr, MR, CC, CC, 0);
    mma_gemm<false><<<dim3(CC/BN, MRT), 256>>>(
        mt, nullptr, Wmod1, bmod1, t1m, nullptr, MR, CC, CC, 0);

    // 6) out = x + (t1a @ Wadd2 + badd2)
    mma_gemm<false><<<dim3(CC/BN, MRT), 256>>>(
        t1a, nullptr, Wadd2, badd2, out, x, MR, CC, CC, 1);

    // 7) out = (out + (t1m @ Wmod2 + bmod2)) / 3
    mma_gemm<false><<<dim3(CC/BN, MRT), 256>>>(
        t1m, nullptr, Wmod2, bmod2, out, out, MR, CC, CC, 2);
}

// round 6
// speedup vs baseline: 4.3090x; 1.5672x over previous
#include <cuda_runtime.h>
#include <cuda_fp16.h>
#include <cstdint>
#include <math.h>

#define BB 8
#define NN 89
#define CC 1024
#define HH 512
#define M_EDGE (BB*NN*NN)   // 63368

// Scratch
__device__ __half g_p [(size_t)M_EDGE * CC];   // 130 MB
__device__ __half g_h1[(size_t)M_EDGE * CC];   // 130 MB
__device__ float  g_h2[(size_t)M_EDGE * HH];   // 130 MB
__device__ float  g_s [M_EDGE];
__device__ __half g_wt1[CC*CC];                // Wa1^T [N=1024,K=1024]
__device__ __half g_wt2[HH*CC];                // Wa2^T [N=512, K=1024]
__device__ float g_at[BB*NN*CC];
__device__ float g_mt[BB*NN*CC];
__device__ float g_t1a[BB*NN*CC];
__device__ float g_t1m[BB*NN*CC];

// ---------------------------------------------------------------------------
__device__ __forceinline__ unsigned f2tf32(float x){
    unsigned r; asm("cvt.rna.tf32.f32 %0, %1;" : "=r"(r) : "f"(x)); return r;
}
__device__ __forceinline__ float4 round4(float4 v){
    return make_float4(__uint_as_float(f2tf32(v.x)), __uint_as_float(f2tf32(v.y)),
                       __uint_as_float(f2tf32(v.z)), __uint_as_float(f2tf32(v.w)));
}
__device__ __forceinline__ uint32_t smem_u32(const void* p){
    uint32_t a;
    asm("{ .reg .u64 t; cvta.to.shared.u64 t, %1; cvt.u32.u64 %0, t; }" : "=r"(a) : "l"(p));
    return a;
}
__device__ __forceinline__ void hmma(float c[4], const uint32_t a[4], const uint32_t b[2]){
    asm volatile("mma.sync.aligned.m16n8k16.row.col.f32.f16.f16.f32 "
        "{%0,%1,%2,%3}, {%4,%5,%6,%7}, {%8,%9}, {%0,%1,%2,%3};"
        : "+f"(c[0]), "+f"(c[1]), "+f"(c[2]), "+f"(c[3])
        : "r"(a[0]), "r"(a[1]), "r"(a[2]), "r"(a[3]), "r"(b[0]), "r"(b[1]));
}
__device__ __forceinline__ void ldmx4(uint32_t a[4], uint32_t addr){
    asm volatile("ldmatrix.sync.aligned.m8n8.x4.shared.b16 {%0,%1,%2,%3}, [%4];"
        : "=r"(a[0]), "=r"(a[1]), "=r"(a[2]), "=r"(a[3]) : "r"(addr));
}
__device__ __forceinline__ uint32_t pack_half2(float a, float b){
    __half2 h = __floats2half2_rn(a, b);
    return *reinterpret_cast<uint32_t*>(&h);
}

// ---------------------------------------------------------------------------
// p[row,:] = half( x[b,j,:] * x[b,i,:] )
// ---------------------------------------------------------------------------
__global__ void __launch_bounds__(256) prod_kernel(const float* __restrict__ x, __half* __restrict__ p){
    const int row = blockIdx.x, seg = threadIdx.x;
    int b = row / (NN*NN), rem = row - b*(NN*NN), j = rem / NN, i = rem - j*NN;
    const float4 vj = ((const float4*)(x + (size_t)(b*NN + j)*CC))[seg];
    const float4 vi = ((const float4*)(x + (size_t)(b*NN + i)*CC))[seg];
    uint2 pk = make_uint2(pack_half2(vj.x*vi.x, vj.y*vi.y),
                          pack_half2(vj.z*vi.z, vj.w*vi.w));
    ((uint2*)p)[(size_t)row * 256 + seg] = pk;
}

// ---------------------------------------------------------------------------
// Wt[n,k] = half( W[k,n] )
// ---------------------------------------------------------------------------
__global__ void transpose_half(const float* __restrict__ W, __half* __restrict__ Wt, int K, int N){
    __shared__ float tile[32][33];
    int k0 = blockIdx.x*32, n0 = blockIdx.y*32;
    int tx = threadIdx.x, ty = threadIdx.y;
    #pragma unroll
    for (int r = 0; r < 32; r += 8)
        tile[ty + r][tx] = W[(size_t)(k0 + ty + r)*N + n0 + tx];
    __syncthreads();
    #pragma unroll
    for (int r = 0; r < 32; r += 8)
        Wt[(size_t)(n0 + ty + r)*K + k0 + tx] = __float2half(tile[tx][ty + r]);
}

// ---------------------------------------------------------------------------
// FP16 HMMA GEMM:  C = relu(A @ Bt^T + bias)
//   A:[M,K] half row-major, Bt:[N,K] half row-major, bias fp32.
// BM=128, BN=128, BK=32, 8 warps (2x4), warp tile 64x32, double buffer.
// LDH=40 halfs (80B rows -> conflict-free ldmatrix / B loads).
// ---------------------------------------------------------------------------
#define LDH 40

template<bool OUT_HALF>
__global__ void __launch_bounds__(256) hgemm(
    const __half* __restrict__ A, const __half* __restrict__ Bt,
    const float* __restrict__ bias, void* __restrict__ Cout,
    int M, int K, int N)
{
    __shared__ __align__(16) __half As[2][128*LDH];
    __shared__ __align__(16) __half Bs[2][128*LDH];

    const int t = threadIdx.x, warp = t >> 5, lane = t & 31;
    const int g = lane >> 2, tig = lane & 3;
    const int wm = (warp >> 2) * 64, wn = (warp & 3) * 32;
    const int mBase = blockIdx.y * 128, nBase = blockIdx.x * 128;

    // global loaders: each thread = half a row-tile (16 halfs = 2 uint4)
    const int lrow = t >> 1;
    const int lk   = (t & 1) * 16;
    const int garow = mBase + lrow;
    const bool va = garow < M;
    const __half* agp = va ? A + (size_t)garow * K + lk : nullptr;
    const __half* bgp = Bt + (size_t)(nBase + lrow) * K + lk;

    uint32_t uA[2] = { smem_u32(&As[0][0]), smem_u32(&As[1][0]) };
    const int laneR = lane & 15;
    const int laneK = (lane >> 4) << 3;

    uint4 ar0, ar1, br0, br1;
    auto load_g = [&](int k0){
        if (va){ ar0 = *(const uint4*)(agp + k0); ar1 = *(const uint4*)(agp + k0 + 8); }
        else   { ar0 = make_uint4(0,0,0,0); ar1 = ar0; }
        br0 = *(const uint4*)(bgp + k0); br1 = *(const uint4*)(bgp + k0 + 8);
    };
    auto store_s = [&](int buf){
        *(uint4*)&As[buf][lrow*LDH + lk    ] = ar0;
        *(uint4*)&As[buf][lrow*LDH + lk + 8] = ar1;
        *(uint4*)&Bs[buf][lrow*LDH + lk    ] = br0;
        *(uint4*)&Bs[buf][lrow*LDH + lk + 8] = br1;
    };

    float acc[4][4][4];
    #pragma unroll
    for (int mi = 0; mi < 4; mi++)
        #pragma unroll
        for (int ni = 0; ni < 4; ni++)
            #pragma unroll
            for (int q = 0; q < 4; q++) acc[mi][ni][q] = 0.f;

    load_g(0); store_s(0); __syncthreads();

    const int KT = K / 32;
    for (int kt = 0; kt < KT; kt++){
        const int cur = kt & 1;
        if (kt + 1 < KT) load_g((kt + 1) * 32);

        #pragma unroll
        for (int ko = 0; ko < 32; ko += 16){
            uint32_t af[4][4], bf[4][2];
            #pragma unroll
            for (int mi = 0; mi < 4; mi++)
                ldmx4(af[mi], uA[cur] + (uint32_t)(((wm + mi*16 + laneR)*LDH + ko + laneK) * 2));
            #pragma unroll
            for (int ni = 0; ni < 4; ni++){
                const __half* bp = &Bs[cur][(wn + ni*8 + g)*LDH + ko + 2*tig];
                bf[ni][0] = *(const uint32_t*)bp;
                bf[ni][1] = *(const uint32_t*)(bp + 8);
            }
            #pragma unroll
            for (int mi = 0; mi < 4; mi++)
                #pragma unroll
                for (int ni = 0; ni < 4; ni++)
                    hmma(acc[mi][ni], af[mi], bf[ni]);
        }

        if (kt + 1 < KT) store_s((kt + 1) & 1);
        __syncthreads();
    }

    // epilogue: relu(acc + bias); half or fp32 out
    #pragma unroll
    for (int mi = 0; mi < 4; mi++)
        #pragma unroll
        for (int ni = 0; ni < 4; ni++){
            const int cb = nBase + wn + ni*8 + 2*tig;
            const float2 bs = *(const float2*)(bias + cb);
            #pragma unroll
            for (int hh = 0; hh < 2; hh++){
                const int r = mBase + wm + mi*16 + g + hh*8;
                if (r >= M) continue;
                float z0 = fmaxf(acc[mi][ni][hh*2+0] + bs.x, 0.f);
                float z1 = fmaxf(acc[mi][ni][hh*2+1] + bs.y, 0.f);
                if (OUT_HALF){
                    *(uint32_t*)((__half*)Cout + (size_t)r * N + cb) = pack_half2(z0, z1);
                } else {
                    *(float2*)((float*)Cout + (size_t)r * N + cb) = make_float2(z0, z1);
                }
            }
        }
}

// ---------------------------------------------------------------------------
// legacy tf32 GEMM for small 712-row GEMMs (proven)
// ---------------------------------------------------------------------------
__device__ __forceinline__ void mma_frag(float c[4], const unsigned a[4], const unsigned b[2]){
    asm volatile("mma.sync.aligned.m16n8k8.row.col.f32.tf32.tf32.f32 "
        "{%0,%1,%2,%3}, {%4,%5,%6,%7}, {%8,%9}, {%0,%1,%2,%3};\n"
        : "+f"(c[0]), "+f"(c[1]), "+f"(c[2]), "+f"(c[3])
        : "r"(a[0]), "r"(a[1]), "r"(a[2]), "r"(a[3]), "r"(b[0]), "r"(b[1]));
}
__global__ void __launch_bounds__(256) mma_gemm(
    const float* __restrict__ A, const float* __restrict__ Bm,
    const float* __restrict__ bias, float* __restrict__ Cmat,
    const float* __restrict__ aux, int M, int K, int Ncols, int mode)
{
    __shared__ __align__(16) float As[2][16][136];
    __shared__ __align__(16) float Bs[2][16][136];
    const int t = threadIdx.x, warp = t >> 5, lane = t & 31;
    const int g = lane >> 2, tig = lane & 3;
    const int wm = (warp >> 2) * 64, wn = (warp & 3) * 32;
    const int mBase = blockIdx.y * 128, nBase = blockIdx.x * 128;
    const int arow = t >> 2, akq = (t & 3) * 4;
    const int grow0 = mBase + arow, grow1 = grow0 + 64;
    const bool v0 = grow0 < M, v1 = grow1 < M;
    const float* ap0 = v0 ? A + (size_t)grow0 * K : nullptr;
    const float* ap1 = v1 ? A + (size_t)grow1 * K : nullptr;
    const int bkr = t >> 5, bnc = (t & 31) * 4;
    float4 a0s, a1s, b0s, b1s;
    auto load_g = [&](int k0){
        const float4 z = make_float4(0,0,0,0);
        a0s = v0 ? *(const float4*)(ap0 + k0 + akq) : z;
        a1s = v1 ? *(const float4*)(ap1 + k0 + akq) : z;
        b0s = *(const float4*)(Bm + (size_t)(k0 + bkr    ) * Ncols + nBase + bnc);
        b1s = *(const float4*)(Bm + (size_t)(k0 + bkr + 8) * Ncols + nBase + bnc);
    };
    auto store_s = [&](int buf){
        float4 c0 = round4(a0s), c1 = round4(a1s);
        As[buf][akq+0][arow] = c0.x; As[buf][akq+1][arow] = c0.y;
        As[buf][akq+2][arow] = c0.z; As[buf][akq+3][arow] = c0.w;
        As[buf][akq+0][arow+64] = c1.x; As[buf][akq+1][arow+64] = c1.y;
        As[buf][akq+2][arow+64] = c1.z; As[buf][akq+3][arow+64] = c1.w;
        *(float4*)&Bs[buf][bkr][bnc]     = round4(b0s);
        *(float4*)&Bs[buf][bkr + 8][bnc] = round4(b1s);
    };
    float acc[4][4][4];
    #pragma unroll
    for (int mi = 0; mi < 4; mi++)
        #pragma unroll
        for (int ni = 0; ni < 4; ni++)
            #pragma unroll
            for (int q = 0; q < 4; q++) acc[mi][ni][q] = 0.f;
    load_g(0); store_s(0); __syncthreads();
    const int KT = K / 16;
    for (int kt = 0; kt < KT; kt++){
        const int cur = kt & 1;
        if (kt + 1 < KT) load_g((kt + 1) * 16);
        #pragma unroll
        for (int ko = 0; ko < 16; ko += 8){
            unsigned af[4][4], bf[4][2];
            #pragma unroll
            for (int mi = 0; mi < 4; mi++){
                const int m0 = wm + mi*16 + g;
                af[mi][0] = __float_as_uint(As[cur][ko + tig    ][m0    ]);
                af[mi][1] = __float_as_uint(As[cur][ko + tig    ][m0 + 8]);
                af[mi][2] = __float_as_uint(As[cur][ko + tig + 4][m0    ]);
                af[mi][3] = __float_as_uint(As[cur][ko + tig + 4][m0 + 8]);
            }
            #pragma unroll
            for (int ni = 0; ni < 4; ni++){
                const int n0 = wn + ni*8 + g;
                bf[ni][0] = __float_as_uint(Bs[cur][ko + tig    ][n0]);
                bf[ni][1] = __float_as_uint(Bs[cur][ko + tig + 4][n0]);
            }
            #pragma unroll
            for (int mi = 0; mi < 4; mi++)
                #pragma unroll
                for (int ni = 0; ni < 4; ni++)
                    mma_frag(acc[mi][ni], af[mi], bf[ni]);
        }
        if (kt + 1 < KT) store_s((kt + 1) & 1);
        __syncthreads();
    }
    #pragma unroll
    for (int mi = 0; mi < 4; mi++)
        #pragma unroll
        for (int ni = 0; ni < 4; ni++){
            const int cb = nBase + wn + ni*8 + 2*tig;
            const float2 bs = *(const float2*)(bias + cb);
            #pragma unroll
            for (int hh = 0; hh < 2; hh++){
                const int r = mBase + wm + mi*16 + g + hh*8;
                if (r >= M) continue;
                float z0 = acc[mi][ni][hh*2+0] + bs.x;
                float z1 = acc[mi][ni][hh*2+1] + bs.y;
                if (mode == 0){ z0 = fmaxf(z0, 0.f); z1 = fmaxf(z1, 0.f); }
                else {
                    const float2 a = *(const float2*)(aux + (size_t)r * Ncols + cb);
                    z0 += a.x; z1 += a.y;
                    if (mode == 2){ z0 *= (1.f/3.f); z1 *= (1.f/3.f); }
                }
                *(float2*)(Cmat + (size_t)r * Ncols + cb) = make_float2(z0, z1);
            }
        }
}

// ---------------------------------------------------------------------------
// s + aggregation
// ---------------------------------------------------------------------------
__global__ void s_kernel(const float* __restrict__ h2, const float* __restrict__ Wa3,
                         const float* __restrict__ ba3, float* __restrict__ s, int M)
{
    int warp = (blockIdx.x * blockDim.x + threadIdx.x) >> 5;
    int lane = threadIdx.x & 31;
    if (warp >= M) return;
    const float* rowp = h2 + (size_t)warp * HH;
    float acc = 0.f;
    #pragma unroll
    for (int q = 0; q < 4; q++){
        int k = (lane + q*32) * 4;
        float4 hv = *(const float4*)(rowp + k);
        float4 wv = *(const float4*)(Wa3 + k);
        acc += hv.x*wv.x + hv.y*wv.y + hv.z*wv.z + hv.w*wv.w;
    }
    #pragma unroll
    for (int o = 16; o > 0; o >>= 1) acc += __shfl_xor_sync(0xffffffffu, acc, o);
    if (lane == 0) s[warp] = 1.f / (1.f + expf(-(acc + ba3[0])));
}
__global__ void __launch_bounds__(256) agg_kernel(
    const float* __restrict__ x, const float* __restrict__ s,
    const float* __restrict__ adj_add, const float* __restrict__ adj_mod,
    float* __restrict__ at, float* __restrict__ mt)
{
    int bi = blockIdx.x;
    int b = bi / NN, i = bi - b*NN;
    int f = threadIdx.x * 4;
    float4 aa = make_float4(0,0,0,0), mm = make_float4(0,0,0,0);
    for (int j = 0; j < NN; j++){
        float sv = s[(b*NN + j)*NN + i];
        float wa = sv * adj_add[j*NN + i];
        float wm = adj_mod[j*NN + i];
        float4 xv = *(const float4*)(x + (size_t)(b*NN + j)*CC + f);
        aa.x = fmaf(wa, xv.x, aa.x); aa.y = fmaf(wa, xv.y, aa.y);
        aa.z = fmaf(wa, xv.z, aa.z); aa.w = fmaf(wa, xv.w, aa.w);
        mm.x = fmaf(wm, xv.x, mm.x); mm.y = fmaf(wm, xv.y, mm.y);
        mm.z = fmaf(wm, xv.z, mm.z); mm.w = fmaf(wm, xv.w, mm.w);
    }
    float4 xv = *(const float4*)(x + (size_t)bi * CC + f);
    mm.x *= xv.x; mm.y *= xv.y; mm.z *= xv.z; mm.w *= xv.w;
    *(float4*)(at + (size_t)bi * CC + f) = aa;
    *(float4*)(mt + (size_t)bi * CC + f) = mm;
}

// ---------------------------------------------------------------------------
extern "C" void kernel_launch(void* const* d_in, const int* in_sizes, int n_in,
                              void* d_out, int out_size)
{
    const float* x    = (const float*)d_in[0];
    const float* Wa1  = (const float*)d_in[3];
    const float* ba1  = (const float*)d_in[4];
    const float* Wa2  = (const float*)d_in[5];
    const float* ba2  = (const float*)d_in[6];
    const float* Wa3  = (const float*)d_in[7];
    const float* ba3  = (const float*)d_in[8];
    float* out = (float*)d_out;

    __half *p, *h1, *wt1, *wt2;
    float *h2, *sptr, *at, *mt, *t1a, *t1m;
    cudaGetSymbolAddress((void**)&p,   g_p);
    cudaGetSymbolAddress((void**)&h1,  g_h1);
    cudaGetSymbolAddress((void**)&h2,  g_h2);
    cudaGetSymbolAddress((void**)&sptr,g_s);
    cudaGetSymbolAddress((void**)&wt1, g_wt1);
    cudaGetSymbolAddress((void**)&wt2, g_wt2);
    cudaGetSymbolAddress((void**)&at,  g_at);
    cudaGetSymbolAddress((void**)&mt,  g_mt);
    cudaGetSymbolAddress((void**)&t1a, g_t1a);
    cudaGetSymbolAddress((void**)&t1m, g_t1m);

    const int M = M_EDGE, MR = BB * NN;
    const int MT = (M + 127) / 128;   // 496

    // prep: weights -> half [N,K]; edge products -> half
    transpose_half<<<dim3(CC/32, CC/32), dim3(32,8)>>>(Wa1, wt1, CC, CC);
    transpose_half<<<dim3(CC/32, HH/32), dim3(32,8)>>>(Wa2, wt2, CC, HH);
    prod_kernel<<<M, 256>>>(x, p);

    // h1 = relu(p @ Wa1 + ba1)  (half out)
    hgemm<true ><<<dim3(CC/128, MT), 256>>>(p,  wt1, ba1, h1, M, CC, CC);
    // h2 = relu(h1 @ Wa2 + ba2) (fp32 out)
    hgemm<false><<<dim3(HH/128, MT), 256>>>(h1, wt2, ba2, h2, M, CC, HH);

    s_kernel<<<(M*32 + 255)/256, 256>>>(h2, Wa3, ba3, sptr, M);
    agg_kernel<<<MR, 256>>>(x, sptr, (const float*)d_in[1], (const float*)d_in[2], at, mt);

    const int MRT = (MR + 127) / 128; // 6
    mma_gemm<<<dim3(CC/128, MRT), 256>>>(at,  (const float*)d_in[9],  (const float*)d_in[10], t1a, nullptr, MR, CC, CC, 0);
    mma_gemm<<<dim3(CC/128, MRT), 256>>>(mt,  (const float*)d_in[13], (const float*)d_in[14], t1m, nullptr, MR, CC, CC, 0);
    mma_gemm<<<dim3(CC/128, MRT), 256>>>(t1a, (const float*)d_in[11], (const float*)d_in[12], out, x,   MR, CC, CC, 1);
    mma_gemm<<<dim3(CC/128, MRT), 256>>>(t1m, (const float*)d_in[15], (const float*)d_in[16], out, out, MR, CC, CC, 2);
}

// round 7
// speedup vs baseline: 4.7491x; 1.1021x over previous
#include <cuda_runtime.h>
#include <cuda_fp16.h>
#include <cstdint>
#include <math.h>

#define BB 8
#define NN 89
#define CC 1024
#define HH 512
#define M_EDGE (BB*NN*NN)   // 63368

// Scratch
__device__ __half g_p [(size_t)M_EDGE * CC];   // 130 MB
__device__ __half g_h1[(size_t)M_EDGE * CC];   // 130 MB
__device__ float  g_s [M_EDGE];
__device__ float  g_spart[(size_t)8 * M_EDGE]; // s partial sums [8][M]
__device__ __half g_wt1[CC*CC];                // Wa1^T [1024,1024]
__device__ __half g_wt2[HH*CC];                // Wa2^T [512,1024]
__device__ float g_at[BB*NN*CC];
__device__ float g_mt[BB*NN*CC];
__device__ float g_t1a[BB*NN*CC];
__device__ float g_t1m[BB*NN*CC];

// ---------------------------------------------------------------------------
__device__ __forceinline__ unsigned f2tf32(float x){
    unsigned r; asm("cvt.rna.tf32.f32 %0, %1;" : "=r"(r) : "f"(x)); return r;
}
__device__ __forceinline__ float4 round4(float4 v){
    return make_float4(__uint_as_float(f2tf32(v.x)), __uint_as_float(f2tf32(v.y)),
                       __uint_as_float(f2tf32(v.z)), __uint_as_float(f2tf32(v.w)));
}
__device__ __forceinline__ uint32_t smem_u32(const void* p){
    uint32_t a;
    asm("{ .reg .u64 t; cvta.to.shared.u64 t, %1; cvt.u32.u64 %0, t; }" : "=r"(a) : "l"(p));
    return a;
}
__device__ __forceinline__ void hmma(float c[4], const uint32_t a[4], const uint32_t b[2]){
    asm volatile("mma.sync.aligned.m16n8k16.row.col.f32.f16.f16.f32 "
        "{%0,%1,%2,%3}, {%4,%5,%6,%7}, {%8,%9}, {%0,%1,%2,%3};"
        : "+f"(c[0]), "+f"(c[1]), "+f"(c[2]), "+f"(c[3])
        : "r"(a[0]), "r"(a[1]), "r"(a[2]), "r"(a[3]), "r"(b[0]), "r"(b[1]));
}
__device__ __forceinline__ void ldmx4(uint32_t a[4], uint32_t addr){
    asm volatile("ldmatrix.sync.aligned.m8n8.x4.shared.b16 {%0,%1,%2,%3}, [%4];"
        : "=r"(a[0]), "=r"(a[1]), "=r"(a[2]), "=r"(a[3]) : "r"(addr));
}
__device__ __forceinline__ uint32_t pack_half2(float a, float b){
    __half2 h = __floats2half2_rn(a, b);
    return *reinterpret_cast<uint32_t*>(&h);
}
__device__ __forceinline__ void cp16(uint32_t dst, const void* src){
    asm volatile("cp.async.cg.shared.global [%0], [%1], 16;" :: "r"(dst), "l"(src));
}
__device__ __forceinline__ void cp_commit(){ asm volatile("cp.async.commit_group;"); }
template<int NW> __device__ __forceinline__ void cp_wait(){
    asm volatile("cp.async.wait_group %0;" :: "n"(NW));
}

// ---------------------------------------------------------------------------
// p[row,:] = half( x[b,j,:] * x[b,i,:] )
// ---------------------------------------------------------------------------
__global__ void __launch_bounds__(256) prod_kernel(const float* __restrict__ x, __half* __restrict__ p){
    const int row = blockIdx.x, seg = threadIdx.x;
    int b = row / (NN*NN), rem = row - b*(NN*NN), j = rem / NN, i = rem - j*NN;
    const float4 vj = ((const float4*)(x + (size_t)(b*NN + j)*CC))[seg];
    const float4 vi = ((const float4*)(x + (size_t)(b*NN + i)*CC))[seg];
    uint2 pk = make_uint2(pack_half2(vj.x*vi.x, vj.y*vi.y),
                          pack_half2(vj.z*vi.z, vj.w*vi.w));
    ((uint2*)p)[(size_t)row * 256 + seg] = pk;
}

// ---------------------------------------------------------------------------
// Wt[n,k] = half( W[k,n] )
// ---------------------------------------------------------------------------
__global__ void transpose_half(const float* __restrict__ W, __half* __restrict__ Wt, int K, int N){
    __shared__ float tile[32][33];
    int k0 = blockIdx.x*32, n0 = blockIdx.y*32;
    int tx = threadIdx.x, ty = threadIdx.y;
    #pragma unroll
    for (int r = 0; r < 32; r += 8)
        tile[ty + r][tx] = W[(size_t)(k0 + ty + r)*N + n0 + tx];
    __syncthreads();
    #pragma unroll
    for (int r = 0; r < 32; r += 8)
        Wt[(size_t)(n0 + ty + r)*K + k0 + tx] = __float2half(tile[tx][ty + r]);
}

// ---------------------------------------------------------------------------
// FP16 HMMA GEMM v2:  CTA 128x256, BK=32, 3-stage cp.async, warp tile 64x64.
//   A:[M,K] half, Bt:[N,K] half (B^T), bias fp32.
//   MODE 1: C half = relu(acc+bias)
//   MODE 2: no C; spart[col][r] += dot(relu(acc+bias), wvec)  (s fusion)
// ---------------------------------------------------------------------------
#define LDH 40
#define BK 32
#define A_STAGE (128*LDH)   // halfs
#define B_STAGE (256*LDH)   // halfs

template<int MODE>
__global__ void __launch_bounds__(256, 1) hgemm(
    const __half* __restrict__ A, const __half* __restrict__ Bt,
    const float* __restrict__ bias, void* __restrict__ Cout,
    const float* __restrict__ wvec, float* __restrict__ spart,
    int M, int K, int N)
{
    extern __shared__ __half sh[];
    __half* Abase = sh;
    __half* Bbase = sh + 3*A_STAGE;

    const int t = threadIdx.x, warp = t >> 5, lane = t & 31;
    const int g = lane >> 2, tig = lane & 3;
    const int wm = (warp >> 2) * 64, wn = (warp & 3) * 64;
    const int mBase = blockIdx.y * 128, nBase = blockIdx.x * 256;

    // ---- staging maps ----
    const int aRow = t >> 1, aK = (t & 1) * 16;
    int garow = mBase + aRow; if (garow >= M) garow = M - 1;   // clamp (results discarded)
    const __half* agp = A + (size_t)garow * K + aK;
    const uint32_t aDst0 = smem_u32(Abase) + (uint32_t)((aRow*LDH + aK) * 2);
    const __half* bgp = Bt + (size_t)(nBase + t) * K;
    const uint32_t bDst0 = smem_u32(Bbase) + (uint32_t)(t * LDH * 2);

    const uint32_t uA = smem_u32(Abase);
    const uint32_t uB = smem_u32(Bbase);
    const int laneR = lane & 15, laneK = (lane >> 4) << 3;
    const int bg4 = lane >> 3, br = lane & 7;   // ldmatrix-B lane geometry

    auto issue = [&](int kt){
        const int s = kt % 3;
        const int k0 = kt * BK;
        uint32_t da = aDst0 + (uint32_t)(s * A_STAGE * 2);
        cp16(da,      agp + k0);
        cp16(da + 16, agp + k0 + 8);
        uint32_t db = bDst0 + (uint32_t)(s * B_STAGE * 2);
        #pragma unroll
        for (int q = 0; q < 4; q++)
            cp16(db + q*16, bgp + k0 + q*8);
    };

    float acc[4][8][4];
    #pragma unroll
    for (int mi = 0; mi < 4; mi++)
        #pragma unroll
        for (int ni = 0; ni < 8; ni++)
            #pragma unroll
            for (int q = 0; q < 4; q++) acc[mi][ni][q] = 0.f;

    const int KT = K / BK;
    issue(0); cp_commit();
    issue(1); cp_commit();

    for (int kt = 0; kt < KT; kt++){
        cp_wait<1>();
        __syncthreads();
        if (kt + 2 < KT) issue(kt + 2);
        cp_commit();

        const int s = kt % 3;
        const uint32_t uAs = uA + (uint32_t)(s * A_STAGE * 2);
        const uint32_t uBs = uB + (uint32_t)(s * B_STAGE * 2);

        #pragma unroll
        for (int ko = 0; ko < BK; ko += 16){
            uint32_t af[4][4], bf[8][2];
            #pragma unroll
            for (int mi = 0; mi < 4; mi++)
                ldmx4(af[mi], uAs + (uint32_t)(((wm + mi*16 + laneR)*LDH + ko + laneK) * 2));
            #pragma unroll
            for (int nq = 0; nq < 4; nq++){
                uint32_t r4[4];
                int n = wn + nq*16 + (bg4 >> 1)*8 + br;
                int k = ko + (bg4 & 1)*8;
                ldmx4(r4, uBs + (uint32_t)((n*LDH + k) * 2));
                bf[nq*2  ][0] = r4[0]; bf[nq*2  ][1] = r4[1];
                bf[nq*2+1][0] = r4[2]; bf[nq*2+1][1] = r4[3];
            }
            #pragma unroll
            for (int mi = 0; mi < 4; mi++)
                #pragma unroll
                for (int ni = 0; ni < 8; ni++)
                    hmma(acc[mi][ni], af[mi], bf[ni]);
        }
    }

    // ---- epilogue ----
    if (MODE == 1){
        #pragma unroll
        for (int mi = 0; mi < 4; mi++)
            #pragma unroll
            for (int ni = 0; ni < 8; ni++){
                const int cb = nBase + wn + ni*8 + 2*tig;
                const float2 bs = *(const float2*)(bias + cb);
                #pragma unroll
                for (int hh = 0; hh < 2; hh++){
                    const int r = mBase + wm + mi*16 + g + hh*8;
                    if (r >= M) continue;
                    float z0 = fmaxf(acc[mi][ni][hh*2+0] + bs.x, 0.f);
                    float z1 = fmaxf(acc[mi][ni][hh*2+1] + bs.y, 0.f);
                    *(uint32_t*)((__half*)Cout + (size_t)r * N + cb) = pack_half2(z0, z1);
                }
            }
    } else {
        // MODE 2: per-row partial dot with wvec, reduced over tig, no C output
        float rs[4][2];
        #pragma unroll
        for (int mi = 0; mi < 4; mi++){ rs[mi][0] = 0.f; rs[mi][1] = 0.f; }
        #pragma unroll
        for (int mi = 0; mi < 4; mi++)
            #pragma unroll
            for (int ni = 0; ni < 8; ni++){
                const int cb = nBase + wn + ni*8 + 2*tig;
                const float2 bs = *(const float2*)(bias + cb);
                const float2 wv = *(const float2*)(wvec + cb);
                #pragma unroll
                for (int hh = 0; hh < 2; hh++){
                    float z0 = fmaxf(acc[mi][ni][hh*2+0] + bs.x, 0.f);
                    float z1 = fmaxf(acc[mi][ni][hh*2+1] + bs.y, 0.f);
                    rs[mi][hh] += z0*wv.x + z1*wv.y;
                }
            }
        const int col = blockIdx.x * 4 + (warp & 3);
        #pragma unroll
        for (int mi = 0; mi < 4; mi++)
            #pragma unroll
            for (int hh = 0; hh < 2; hh++){
                float v = rs[mi][hh];
                v += __shfl_xor_sync(0xffffffffu, v, 1);
                v += __shfl_xor_sync(0xffffffffu, v, 2);
                const int r = mBase + wm + mi*16 + g + hh*8;
                if (tig == 0 && r < M)
                    spart[(size_t)col * M + r] = v;
            }
    }
}

// ---------------------------------------------------------------------------
// s[r] = sigmoid( sum_c spart[c][r] + ba3 )
// ---------------------------------------------------------------------------
__global__ void s_finalize(const float* __restrict__ spart, const float* __restrict__ ba3,
                           float* __restrict__ s, int M)
{
    int r = blockIdx.x * 256 + threadIdx.x;
    if (r >= M) return;
    float v = ba3[0];
    #pragma unroll
    for (int c = 0; c < 8; c++) v += spart[(size_t)c * M + r];
    s[r] = 1.f / (1.f + expf(-v));
}

// ---------------------------------------------------------------------------
// legacy tf32 GEMM for small 712-row GEMMs (proven)
// ---------------------------------------------------------------------------
__device__ __forceinline__ void mma_frag(float c[4], const unsigned a[4], const unsigned b[2]){
    asm volatile("mma.sync.aligned.m16n8k8.row.col.f32.tf32.tf32.f32 "
        "{%0,%1,%2,%3}, {%4,%5,%6,%7}, {%8,%9}, {%0,%1,%2,%3};\n"
        : "+f"(c[0]), "+f"(c[1]), "+f"(c[2]), "+f"(c[3])
        : "r"(a[0]), "r"(a[1]), "r"(a[2]), "r"(a[3]), "r"(b[0]), "r"(b[1]));
}
__global__ void __launch_bounds__(256) mma_gemm(
    const float* __restrict__ A, const float* __restrict__ Bm,
    const float* __restrict__ bias, float* __restrict__ Cmat,
    const float* __restrict__ aux, int M, int K, int Ncols, int mode)
{
    __shared__ __align__(16) float As[2][16][136];
    __shared__ __align__(16) float Bs[2][16][136];
    const int t = threadIdx.x, warp = t >> 5, lane = t & 31;
    const int g = lane >> 2, tig = lane & 3;
    const int wm = (warp >> 2) * 64, wn = (warp & 3) * 32;
    const int mBase = blockIdx.y * 128, nBase = blockIdx.x * 128;
    const int arow = t >> 2, akq = (t & 3) * 4;
    const int grow0 = mBase + arow, grow1 = grow0 + 64;
    const bool v0 = grow0 < M, v1 = grow1 < M;
    const float* ap0 = v0 ? A + (size_t)grow0 * K : nullptr;
    const float* ap1 = v1 ? A + (size_t)grow1 * K : nullptr;
    const int bkr = t >> 5, bnc = (t & 31) * 4;
    float4 a0s, a1s, b0s, b1s;
    auto load_g = [&](int k0){
        const float4 z = make_float4(0,0,0,0);
        a0s = v0 ? *(const float4*)(ap0 + k0 + akq) : z;
        a1s = v1 ? *(const float4*)(ap1 + k0 + akq) : z;
        b0s = *(const float4*)(Bm + (size_t)(k0 + bkr    ) * Ncols + nBase + bnc);
        b1s = *(const float4*)(Bm + (size_t)(k0 + bkr + 8) * Ncols + nBase + bnc);
    };
    auto store_s = [&](int buf){
        float4 c0 = round4(a0s), c1 = round4(a1s);
        As[buf][akq+0][arow] = c0.x; As[buf][akq+1][arow] = c0.y;
        As[buf][akq+2][arow] = c0.z; As[buf][akq+3][arow] = c0.w;
        As[buf][akq+0][arow+64] = c1.x; As[buf][akq+1][arow+64] = c1.y;
        As[buf][akq+2][arow+64] = c1.z; As[buf][akq+3][arow+64] = c1.w;
        *(float4*)&Bs[buf][bkr][bnc]     = round4(b0s);
        *(float4*)&Bs[buf][bkr + 8][bnc] = round4(b1s);
    };
    float acc[4][4][4];
    #pragma unroll
    for (int mi = 0; mi < 4; mi++)
        #pragma unroll
        for (int ni = 0; ni < 4; ni++)
            #pragma unroll
            for (int q = 0; q < 4; q++) acc[mi][ni][q] = 0.f;
    load_g(0); store_s(0); __syncthreads();
    const int KT = K / 16;
    for (int kt = 0; kt < KT; kt++){
        const int cur = kt & 1;
        if (kt + 1 < KT) load_g((kt + 1) * 16);
        #pragma unroll
        for (int ko = 0; ko < 16; ko += 8){
            unsigned af[4][4], bf[4][2];
            #pragma unroll
            for (int mi = 0; mi < 4; mi++){
                const int m0 = wm + mi*16 + g;
                af[mi][0] = __float_as_uint(As[cur][ko + tig    ][m0    ]);
                af[mi][1] = __float_as_uint(As[cur][ko + tig    ][m0 + 8]);
                af[mi][2] = __float_as_uint(As[cur][ko + tig + 4][m0    ]);
                af[mi][3] = __float_as_uint(As[cur][ko + tig + 4][m0 + 8]);
            }
            #pragma unroll
            for (int ni = 0; ni < 4; ni++){
                const int n0 = wn + ni*8 + g;
                bf[ni][0] = __float_as_uint(Bs[cur][ko + tig    ][n0]);
                bf[ni][1] = __float_as_uint(Bs[cur][ko + tig + 4][n0]);
            }
            #pragma unroll
            for (int mi = 0; mi < 4; mi++)
                #pragma unroll
                for (int ni = 0; ni < 4; ni++)
                    mma_frag(acc[mi][ni], af[mi], bf[ni]);
        }
        if (kt + 1 < KT) store_s((kt + 1) & 1);
        __syncthreads();
    }
    #pragma unroll
    for (int mi = 0; mi < 4; mi++)
        #pragma unroll
        for (int ni = 0; ni < 4; ni++){
            const int cb = nBase + wn + ni*8 + 2*tig;
            const float2 bs = *(const float2*)(bias + cb);
            #pragma unroll
            for (int hh = 0; hh < 2; hh++){
                const int r = mBase + wm + mi*16 + g + hh*8;
                if (r >= M) continue;
                float z0 = acc[mi][ni][hh*2+0] + bs.x;
                float z1 = acc[mi][ni][hh*2+1] + bs.y;
                if (mode == 0){ z0 = fmaxf(z0, 0.f); z1 = fmaxf(z1, 0.f); }
                else {
                    const float2 a = *(const float2*)(aux + (size_t)r * Ncols + cb);
                    z0 += a.x; z1 += a.y;
                    if (mode == 2){ z0 *= (1.f/3.f); z1 *= (1.f/3.f); }
                }
                *(float2*)(Cmat + (size_t)r * Ncols + cb) = make_float2(z0, z1);
            }
        }
}

// ---------------------------------------------------------------------------
// aggregation
// ---------------------------------------------------------------------------
__global__ void __launch_bounds__(256) agg_kernel(
    const float* __restrict__ x, const float* __restrict__ s,
    const float* __restrict__ adj_add, const float* __restrict__ adj_mod,
    float* __restrict__ at, float* __restrict__ mt)
{
    int bi = blockIdx.x;
    int b = bi / NN, i = bi - b*NN;
    int f = threadIdx.x * 4;
    float4 aa = make_float4(0,0,0,0), mm = make_float4(0,0,0,0);
    for (int j = 0; j < NN; j++){
        float sv = s[(b*NN + j)*NN + i];
        float wa = sv * adj_add[j*NN + i];
        float wm = adj_mod[j*NN + i];
        float4 xv = *(const float4*)(x + (size_t)(b*NN + j)*CC + f);
        aa.x = fmaf(wa, xv.x, aa.x); aa.y = fmaf(wa, xv.y, aa.y);
        aa.z = fmaf(wa, xv.z, aa.z); aa.w = fmaf(wa, xv.w, aa.w);
        mm.x = fmaf(wm, xv.x, mm.x); mm.y = fmaf(wm, xv.y, mm.y);
        mm.z = fmaf(wm, xv.z, mm.z); mm.w = fmaf(wm, xv.w, mm.w);
    }
    float4 xv = *(const float4*)(x + (size_t)bi * CC + f);
    mm.x *= xv.x; mm.y *= xv.y; mm.z *= xv.z; mm.w *= xv.w;
    *(float4*)(at + (size_t)bi * CC + f) = aa;
    *(float4*)(mt + (size_t)bi * CC + f) = mm;
}

// ---------------------------------------------------------------------------
extern "C" void kernel_launch(void* const* d_in, const int* in_sizes, int n_in,
                              void* d_out, int out_size)
{
    const float* x    = (const float*)d_in[0];
    const float* Wa1  = (const float*)d_in[3];
    const float* ba1  = (const float*)d_in[4];
    const float* Wa2  = (const float*)d_in[5];
    const float* ba2  = (const float*)d_in[6];
    const float* Wa3  = (const float*)d_in[7];
    const float* ba3  = (const float*)d_in[8];
    float* out = (float*)d_out;

    __half *p, *h1, *wt1, *wt2;
    float *sptr, *spart, *at, *mt, *t1a, *t1m;
    cudaGetSymbolAddress((void**)&p,    g_p);
    cudaGetSymbolAddress((void**)&h1,   g_h1);
    cudaGetSymbolAddress((void**)&sptr, g_s);
    cudaGetSymbolAddress((void**)&spart,g_spart);
    cudaGetSymbolAddress((void**)&wt1,  g_wt1);
    cudaGetSymbolAddress((void**)&wt2,  g_wt2);
    cudaGetSymbolAddress((void**)&at,   g_at);
    cudaGetSymbolAddress((void**)&mt,   g_mt);
    cudaGetSymbolAddress((void**)&t1a,  g_t1a);
    cudaGetSymbolAddress((void**)&t1m,  g_t1m);

    const int M = M_EDGE, MR = BB * NN;
    const int MT = (M + 127) / 128;   // 496
    const int SMEM = 3 * (A_STAGE + B_STAGE) * 2;   // 92160 B

    cudaFuncSetAttribute(hgemm<1>, cudaFuncAttributeMaxDynamicSharedMemorySize, SMEM);
    cudaFuncSetAttribute(hgemm<2>, cudaFuncAttributeMaxDynamicSharedMemorySize, SMEM);

    // prep
    transpose_half<<<dim3(CC/32, CC/32), dim3(32,8)>>>(Wa1, wt1, CC, CC);
    transpose_half<<<dim3(CC/32, HH/32), dim3(32,8)>>>(Wa2, wt2, CC, HH);
    prod_kernel<<<M, 256>>>(x, p);

    // h1 = relu(p @ Wa1 + ba1)   [half out]
    hgemm<1><<<dim3(CC/256, MT), 256, SMEM>>>(p, wt1, ba1, h1, nullptr, nullptr, M, CC, CC);
    // s partials: relu(h1 @ Wa2 + ba2) . Wa3  (h2 never materialized)
    hgemm<2><<<dim3(HH/256, MT), 256, SMEM>>>(h1, wt2, ba2, nullptr, Wa3, spart, M, CC, HH);
    s_finalize<<<(M + 255)/256, 256>>>(spart, ba3, sptr, M);

    agg_kernel<<<MR, 256>>>(x, sptr, (const float*)d_in[1], (const float*)d_in[2], at, mt);

    const int MRT = (MR + 127) / 128; // 6
    mma_gemm<<<dim3(CC/128, MRT), 256>>>(at,  (const float*)d_in[9],  (const float*)d_in[10], t1a, nullptr, MR, CC, CC, 0);
    mma_gemm<<<dim3(CC/128, MRT), 256>>>(mt,  (const float*)d_in[13], (const float*)d_in[14], t1m, nullptr, MR, CC, CC, 0);
    mma_gemm<<<dim3(CC/128, MRT), 256>>>(t1a, (const float*)d_in[11], (const float*)d_in[12], out, x,   MR, CC, CC, 1);
    mma_gemm<<<dim3(CC/128, MRT), 256>>>(t1m, (const float*)d_in[15], (const float*)d_in[16], out, out, MR, CC, CC, 2);
}

// round 8
// speedup vs baseline: 4.7841x; 1.0074x over previous
#include <cuda_runtime.h>
#include <cuda_fp16.h>
#include <cstdint>
#include <math.h>

#define BB 8
#define NN 89
#define CC 1024
#define HH 512
#define M_EDGE (BB*NN*NN)   // 63368

// Scratch
__device__ __half g_p [(size_t)M_EDGE * CC];   // 130 MB
__device__ __half g_h1[(size_t)M_EDGE * CC];   // 130 MB
__device__ float  g_spart[(size_t)8 * M_EDGE]; // s partial sums [8][M]
__device__ __half g_wt1[CC*CC];                // Wa1^T [1024,1024]
__device__ __half g_wt2[HH*CC];                // Wa2^T [512,1024]
__device__ float g_at[BB*NN*CC];
__device__ float g_mt[BB*NN*CC];
__device__ float g_t1a[BB*NN*CC];
__device__ float g_t1m[BB*NN*CC];

// ---------------------------------------------------------------------------
__device__ __forceinline__ unsigned f2tf32(float x){
    unsigned r; asm("cvt.rna.tf32.f32 %0, %1;" : "=r"(r) : "f"(x)); return r;
}
__device__ __forceinline__ float4 round4(float4 v){
    return make_float4(__uint_as_float(f2tf32(v.x)), __uint_as_float(f2tf32(v.y)),
                       __uint_as_float(f2tf32(v.z)), __uint_as_float(f2tf32(v.w)));
}
__device__ __forceinline__ uint32_t smem_u32(const void* p){
    uint32_t a;
    asm("{ .reg .u64 t; cvta.to.shared.u64 t, %1; cvt.u32.u64 %0, t; }" : "=r"(a) : "l"(p));
    return a;
}
__device__ __forceinline__ void hmma(float c[4], const uint32_t a[4], const uint32_t b[2]){
    asm volatile("mma.sync.aligned.m16n8k16.row.col.f32.f16.f16.f32 "
        "{%0,%1,%2,%3}, {%4,%5,%6,%7}, {%8,%9}, {%0,%1,%2,%3};"
        : "+f"(c[0]), "+f"(c[1]), "+f"(c[2]), "+f"(c[3])
        : "r"(a[0]), "r"(a[1]), "r"(a[2]), "r"(a[3]), "r"(b[0]), "r"(b[1]));
}
__device__ __forceinline__ void ldmx4(uint32_t a[4], uint32_t addr){
    asm volatile("ldmatrix.sync.aligned.m8n8.x4.shared.b16 {%0,%1,%2,%3}, [%4];"
        : "=r"(a[0]), "=r"(a[1]), "=r"(a[2]), "=r"(a[3]) : "r"(addr));
}
__device__ __forceinline__ uint32_t pack_half2(float a, float b){
    __half2 h = __floats2half2_rn(a, b);
    return *reinterpret_cast<uint32_t*>(&h);
}
__device__ __forceinline__ void cp16(uint32_t dst, const void* src){
    asm volatile("cp.async.cg.shared.global [%0], [%1], 16;" :: "r"(dst), "l"(src));
}
__device__ __forceinline__ void cp_commit(){ asm volatile("cp.async.commit_group;"); }
template<int NW> __device__ __forceinline__ void cp_wait(){
    asm volatile("cp.async.wait_group %0;" :: "n"(NW));
}

// ---------------------------------------------------------------------------
// p[row,:] = half( x[b,j,:] * x[b,i,:] )
// ---------------------------------------------------------------------------
__global__ void __launch_bounds__(256) prod_kernel(const float* __restrict__ x, __half* __restrict__ p){
    const int row = blockIdx.x, seg = threadIdx.x;
    int b = row / (NN*NN), rem = row - b*(NN*NN), j = rem / NN, i = rem - j*NN;
    const float4 vj = ((const float4*)(x + (size_t)(b*NN + j)*CC))[seg];
    const float4 vi = ((const float4*)(x + (size_t)(b*NN + i)*CC))[seg];
    uint2 pk = make_uint2(pack_half2(vj.x*vi.x, vj.y*vi.y),
                          pack_half2(vj.z*vi.z, vj.w*vi.w));
    ((uint2*)p)[(size_t)row * 256 + seg] = pk;
}

// ---------------------------------------------------------------------------
// Wt[n,k] = half( W[k,n] )
// ---------------------------------------------------------------------------
__global__ void transpose_half(const float* __restrict__ W, __half* __restrict__ Wt, int K, int N){
    __shared__ float tile[32][33];
    int k0 = blockIdx.x*32, n0 = blockIdx.y*32;
    int tx = threadIdx.x, ty = threadIdx.y;
    #pragma unroll
    for (int r = 0; r < 32; r += 8)
        tile[ty + r][tx] = W[(size_t)(k0 + ty + r)*N + n0 + tx];
    __syncthreads();
    #pragma unroll
    for (int r = 0; r < 32; r += 8)
        Wt[(size_t)(n0 + ty + r)*K + k0 + tx] = __float2half(tile[tx][ty + r]);
}

// ---------------------------------------------------------------------------
// FP16 HMMA GEMM v3:  CTA 128x256, BK=64, 3-stage cp.async, warp tile 64x64,
// fragment double-buffering inside each stage.
//   MODE 1: C half = relu(acc+bias)
//   MODE 2: no C; spart[col][r] = dot(relu(acc+bias), wvec)
// ---------------------------------------------------------------------------
#define LDH 72
#define BK 64
#define A_STAGE (128*LDH)   // halfs
#define B_STAGE (256*LDH)   // halfs

template<int MODE>
__global__ void __launch_bounds__(256, 1) hgemm(
    const __half* __restrict__ A, const __half* __restrict__ Bt,
    const float* __restrict__ bias, void* __restrict__ Cout,
    const float* __restrict__ wvec, float* __restrict__ spart,
    int M, int K, int N)
{
    extern __shared__ __half sh[];
    __half* Abase = sh;
    __half* Bbase = sh + 3*A_STAGE;

    const int t = threadIdx.x, warp = t >> 5, lane = t & 31;
    const int g = lane >> 2, tig = lane & 3;
    const int wm = (warp >> 2) * 64, wn = (warp & 3) * 64;
    const int mBase = blockIdx.y * 128, nBase = blockIdx.x * 256;

    // staging maps: A 128 rows x 64 halfs (thread: row=t>>1, 32 halfs)
    const int aRow = t >> 1, aK0 = (t & 1) * 32;
    int garow = mBase + aRow; if (garow >= M) garow = M - 1;
    const __half* agp = A + (size_t)garow * K + aK0;
    const uint32_t aDst0 = smem_u32(Abase) + (uint32_t)((aRow*LDH + aK0) * 2);
    const __half* bgp = Bt + (size_t)(nBase + t) * K;
    const uint32_t bDst0 = smem_u32(Bbase) + (uint32_t)(t * LDH * 2);

    const uint32_t uA = smem_u32(Abase);
    const uint32_t uB = smem_u32(Bbase);
    const int laneR = lane & 15, laneK = (lane >> 4) << 3;
    const int bg4 = lane >> 3, br = lane & 7;

    auto issue = [&](int kt){
        const int s = kt % 3;
        const int k0 = kt * BK;
        uint32_t da = aDst0 + (uint32_t)(s * A_STAGE * 2);
        #pragma unroll
        for (int q = 0; q < 4; q++) cp16(da + q*16, agp + k0 + q*8);
        uint32_t db = bDst0 + (uint32_t)(s * B_STAGE * 2);
        #pragma unroll
        for (int q = 0; q < 8; q++) cp16(db + q*16, bgp + k0 + q*8);
    };

    float acc[4][8][4];
    #pragma unroll
    for (int mi = 0; mi < 4; mi++)
        #pragma unroll
        for (int ni = 0; ni < 8; ni++)
            #pragma unroll
            for (int q = 0; q < 4; q++) acc[mi][ni][q] = 0.f;

    uint32_t af[2][4][4], bf[2][8][2];

    auto load_frags = [&](int buf, uint32_t uAs, uint32_t uBs, int ko){
        #pragma unroll
        for (int mi = 0; mi < 4; mi++)
            ldmx4(af[buf][mi], uAs + (uint32_t)(((wm + mi*16 + laneR)*LDH + ko + laneK) * 2));
        #pragma unroll
        for (int nq = 0; nq < 4; nq++){
            uint32_t r4[4];
            int n = wn + nq*16 + (bg4 >> 1)*8 + br;
            int k = ko + (bg4 & 1)*8;
            ldmx4(r4, uBs + (uint32_t)((n*LDH + k) * 2));
            bf[buf][nq*2  ][0] = r4[0]; bf[buf][nq*2  ][1] = r4[1];
            bf[buf][nq*2+1][0] = r4[2]; bf[buf][nq*2+1][1] = r4[3];
        }
    };

    const int KT = K / BK;   // 16
    issue(0); cp_commit();
    issue(1); cp_commit();

    for (int kt = 0; kt < KT; kt++){
        cp_wait<1>();
        __syncthreads();
        if (kt + 2 < KT) issue(kt + 2);
        cp_commit();

        const int s = kt % 3;
        const uint32_t uAs = uA + (uint32_t)(s * A_STAGE * 2);
        const uint32_t uBs = uB + (uint32_t)(s * B_STAGE * 2);

        load_frags(0, uAs, uBs, 0);
        #pragma unroll
        for (int ko16 = 0; ko16 < 4; ko16++){
            const int buf = ko16 & 1;
            if (ko16 < 3) load_frags(buf ^ 1, uAs, uBs, (ko16 + 1) * 16);
            #pragma unroll
            for (int mi = 0; mi < 4; mi++)
                #pragma unroll
                for (int ni = 0; ni < 8; ni++)
                    hmma(acc[mi][ni], af[buf][mi], bf[buf][ni]);
        }
    }

    // ---- epilogue ----
    if (MODE == 1){
        #pragma unroll
        for (int mi = 0; mi < 4; mi++)
            #pragma unroll
            for (int ni = 0; ni < 8; ni++){
                const int cb = nBase + wn + ni*8 + 2*tig;
                const float2 bs = *(const float2*)(bias + cb);
                #pragma unroll
                for (int hh = 0; hh < 2; hh++){
                    const int r = mBase + wm + mi*16 + g + hh*8;
                    if (r >= M) continue;
                    float z0 = fmaxf(acc[mi][ni][hh*2+0] + bs.x, 0.f);
                    float z1 = fmaxf(acc[mi][ni][hh*2+1] + bs.y, 0.f);
                    *(uint32_t*)((__half*)Cout + (size_t)r * N + cb) = pack_half2(z0, z1);
                }
            }
    } else {
        float rs[4][2];
        #pragma unroll
        for (int mi = 0; mi < 4; mi++){ rs[mi][0] = 0.f; rs[mi][1] = 0.f; }
        #pragma unroll
        for (int mi = 0; mi < 4; mi++)
            #pragma unroll
            for (int ni = 0; ni < 8; ni++){
                const int cb = nBase + wn + ni*8 + 2*tig;
                const float2 bs = *(const float2*)(bias + cb);
                const float2 wv = *(const float2*)(wvec + cb);
                #pragma unroll
                for (int hh = 0; hh < 2; hh++){
                    float z0 = fmaxf(acc[mi][ni][hh*2+0] + bs.x, 0.f);
                    float z1 = fmaxf(acc[mi][ni][hh*2+1] + bs.y, 0.f);
                    rs[mi][hh] += z0*wv.x + z1*wv.y;
                }
            }
        const int col = blockIdx.x * 4 + (warp & 3);
        #pragma unroll
        for (int mi = 0; mi < 4; mi++)
            #pragma unroll
            for (int hh = 0; hh < 2; hh++){
                float v = rs[mi][hh];
                v += __shfl_xor_sync(0xffffffffu, v, 1);
                v += __shfl_xor_sync(0xffffffffu, v, 2);
                const int r = mBase + wm + mi*16 + g + hh*8;
                if (tig == 0 && r < M)
                    spart[(size_t)col * M + r] = v;
            }
    }
}

// ---------------------------------------------------------------------------
// legacy tf32 GEMM for small 712-row GEMMs. blockIdx.z selects problem
// (dual-launch merge for the independent layer-1 pair).
// ---------------------------------------------------------------------------
__device__ __forceinline__ void mma_frag(float c[4], const unsigned a[4], const unsigned b[2]){
    asm volatile("mma.sync.aligned.m16n8k8.row.col.f32.tf32.tf32.f32 "
        "{%0,%1,%2,%3}, {%4,%5,%6,%7}, {%8,%9}, {%0,%1,%2,%3};\n"
        : "+f"(c[0]), "+f"(c[1]), "+f"(c[2]), "+f"(c[3])
        : "r"(a[0]), "r"(a[1]), "r"(a[2]), "r"(a[3]), "r"(b[0]), "r"(b[1]));
}
__global__ void __launch_bounds__(256) mma_gemm(
    const float* __restrict__ A0, const float* __restrict__ A1,
    const float* __restrict__ B0, const float* __restrict__ B1,
    const float* __restrict__ bias0, const float* __restrict__ bias1,
    float* __restrict__ C0, float* __restrict__ C1,
    const float* __restrict__ aux, int M, int K, int Ncols, int mode)
{
    const float* A    = blockIdx.z ? A1 : A0;
    const float* Bm   = blockIdx.z ? B1 : B0;
    const float* bias = blockIdx.z ? bias1 : bias0;
    float* Cmat       = blockIdx.z ? C1 : C0;

    __shared__ __align__(16) float As[2][16][136];
    __shared__ __align__(16) float Bs[2][16][136];
    const int t = threadIdx.x, warp = t >> 5, lane = t & 31;
    const int g = lane >> 2, tig = lane & 3;
    const int wm = (warp >> 2) * 64, wn = (warp & 3) * 32;
    const int mBase = blockIdx.y * 128, nBase = blockIdx.x * 128;
    const int arow = t >> 2, akq = (t & 3) * 4;
    const int grow0 = mBase + arow, grow1 = grow0 + 64;
    const bool v0 = grow0 < M, v1 = grow1 < M;
    const float* ap0 = v0 ? A + (size_t)grow0 * K : nullptr;
    const float* ap1 = v1 ? A + (size_t)grow1 * K : nullptr;
    const int bkr = t >> 5, bnc = (t & 31) * 4;
    float4 a0s, a1s, b0s, b1s;
    auto load_g = [&](int k0){
        const float4 z = make_float4(0,0,0,0);
        a0s = v0 ? *(const float4*)(ap0 + k0 + akq) : z;
        a1s = v1 ? *(const float4*)(ap1 + k0 + akq) : z;
        b0s = *(const float4*)(Bm + (size_t)(k0 + bkr    ) * Ncols + nBase + bnc);
        b1s = *(const float4*)(Bm + (size_t)(k0 + bkr + 8) * Ncols + nBase + bnc);
    };
    auto store_s = [&](int buf){
        float4 c0 = round4(a0s), c1 = round4(a1s);
        As[buf][akq+0][arow] = c0.x; As[buf][akq+1][arow] = c0.y;
        As[buf][akq+2][arow] = c0.z; As[buf][akq+3][arow] = c0.w;
        As[buf][akq+0][arow+64] = c1.x; As[buf][akq+1][arow+64] = c1.y;
        As[buf][akq+2][arow+64] = c1.z; As[buf][akq+3][arow+64] = c1.w;
        *(float4*)&Bs[buf][bkr][bnc]     = round4(b0s);
        *(float4*)&Bs[buf][bkr + 8][bnc] = round4(b1s);
    };
    float acc[4][4][4];
    #pragma unroll
    for (int mi = 0; mi < 4; mi++)
        #pragma unroll
        for (int ni = 0; ni < 4; ni++)
            #pragma unroll
            for (int q = 0; q < 4; q++) acc[mi][ni][q] = 0.f;
    load_g(0); store_s(0); __syncthreads();
    const int KT = K / 16;
    for (int kt = 0; kt < KT; kt++){
        const int cur = kt & 1;
        if (kt + 1 < KT) load_g((kt + 1) * 16);
        #pragma unroll
        for (int ko = 0; ko < 16; ko += 8){
            unsigned af[4][4], bf[4][2];
            #pragma unroll
            for (int mi = 0; mi < 4; mi++){
                const int m0 = wm + mi*16 + g;
                af[mi][0] = __float_as_uint(As[cur][ko + tig    ][m0    ]);
                af[mi][1] = __float_as_uint(As[cur][ko + tig    ][m0 + 8]);
                af[mi][2] = __float_as_uint(As[cur][ko + tig + 4][m0    ]);
                af[mi][3] = __float_as_uint(As[cur][ko + tig + 4][m0 + 8]);
            }
            #pragma unroll
            for (int ni = 0; ni < 4; ni++){
                const int n0 = wn + ni*8 + g;
                bf[ni][0] = __float_as_uint(Bs[cur][ko + tig    ][n0]);
                bf[ni][1] = __float_as_uint(Bs[cur][ko + tig + 4][n0]);
            }
            #pragma unroll
            for (int mi = 0; mi < 4; mi++)
                #pragma unroll
                for (int ni = 0; ni < 4; ni++)
                    mma_frag(acc[mi][ni], af[mi], bf[ni]);
        }
        if (kt + 1 < KT) store_s((kt + 1) & 1);
        __syncthreads();
    }
    #pragma unroll
    for (int mi = 0; mi < 4; mi++)
        #pragma unroll
        for (int ni = 0; ni < 4; ni++){
            const int cb = nBase + wn + ni*8 + 2*tig;
            const float2 bs = *(const float2*)(bias + cb);
            #pragma unroll
            for (int hh = 0; hh < 2; hh++){
                const int r = mBase + wm + mi*16 + g + hh*8;
                if (r >= M) continue;
                float z0 = acc[mi][ni][hh*2+0] + bs.x;
                float z1 = acc[mi][ni][hh*2+1] + bs.y;
                if (mode == 0){ z0 = fmaxf(z0, 0.f); z1 = fmaxf(z1, 0.f); }
                else {
                    const float2 a = *(const float2*)(aux + (size_t)r * Ncols + cb);
                    z0 += a.x; z1 += a.y;
                    if (mode == 2){ z0 *= (1.f/3.f); z1 *= (1.f/3.f); }
                }
                *(float2*)(Cmat + (size_t)r * Ncols + cb) = make_float2(z0, z1);
            }
        }
}

// ---------------------------------------------------------------------------
// aggregation with fused s finalize: s[b,j,i] = sigmoid(ba3 + sum_c spart)
// ---------------------------------------------------------------------------
__global__ void __launch_bounds__(256) agg_kernel(
    const float* __restrict__ x, const float* __restrict__ spart,
    const float* __restrict__ ba3,
    const float* __restrict__ adj_add, const float* __restrict__ adj_mod,
    float* __restrict__ at, float* __restrict__ mt)
{
    __shared__ float sv_sh[NN];
    int bi = blockIdx.x;
    int b = bi / NN, i = bi - b*NN;
    // threads 0..88 compute s for all j (row = (b*NN+j)*NN + i)
    if (threadIdx.x < NN){
        int row = (b*NN + threadIdx.x)*NN + i;
        float v = ba3[0];
        #pragma unroll
        for (int c = 0; c < 8; c++) v += spart[(size_t)c * M_EDGE + row];
        sv_sh[threadIdx.x] = 1.f / (1.f + expf(-v));
    }
    __syncthreads();

    int f = threadIdx.x * 4;
    float4 aa = make_float4(0,0,0,0), mm = make_float4(0,0,0,0);
    for (int j = 0; j < NN; j++){
        float wa = sv_sh[j] * adj_add[j*NN + i];
        float wm = adj_mod[j*NN + i];
        float4 xv = *(const float4*)(x + (size_t)(b*NN + j)*CC + f);
        aa.x = fmaf(wa, xv.x, aa.x); aa.y = fmaf(wa, xv.y, aa.y);
        aa.z = fmaf(wa, xv.z, aa.z); aa.w = fmaf(wa, xv.w, aa.w);
        mm.x = fmaf(wm, xv.x, mm.x); mm.y = fmaf(wm, xv.y, mm.y);
        mm.z = fmaf(wm, xv.z, mm.z); mm.w = fmaf(wm, xv.w, mm.w);
    }
    float4 xv = *(const float4*)(x + (size_t)bi * CC + f);
    mm.x *= xv.x; mm.y *= xv.y; mm.z *= xv.z; mm.w *= xv.w;
    *(float4*)(at + (size_t)bi * CC + f) = aa;
    *(float4*)(mt + (size_t)bi * CC + f) = mm;
}

// ---------------------------------------------------------------------------
extern "C" void kernel_launch(void* const* d_in, const int* in_sizes, int n_in,
                              void* d_out, int out_size)
{
    const float* x    = (const float*)d_in[0];
    const float* Wa1  = (const float*)d_in[3];
    const float* ba1  = (const float*)d_in[4];
    const float* Wa2  = (const float*)d_in[5];
    const float* ba2  = (const float*)d_in[6];
    const float* Wa3  = (const float*)d_in[7];
    const float* ba3  = (const float*)d_in[8];
    float* out = (float*)d_out;

    __half *p, *h1, *wt1, *wt2;
    float *spart, *at, *mt, *t1a, *t1m;
    cudaGetSymbolAddress((void**)&p,    g_p);
    cudaGetSymbolAddress((void**)&h1,   g_h1);
    cudaGetSymbolAddress((void**)&spart,g_spart);
    cudaGetSymbolAddress((void**)&wt1,  g_wt1);
    cudaGetSymbolAddress((void**)&wt2,  g_wt2);
    cudaGetSymbolAddress((void**)&at,   g_at);
    cudaGetSymbolAddress((void**)&mt,   g_mt);
    cudaGetSymbolAddress((void**)&t1a,  g_t1a);
    cudaGetSymbolAddress((void**)&t1m,  g_t1m);

    const int M = M_EDGE, MR = BB * NN;
    const int MT = (M + 127) / 128;   // 496
    const int SMEM = 3 * (A_STAGE + B_STAGE) * 2;   // 165888 B

    cudaFuncSetAttribute(hgemm<1>, cudaFuncAttributeMaxDynamicSharedMemorySize, SMEM);
    cudaFuncSetAttribute(hgemm<2>, cudaFuncAttributeMaxDynamicSharedMemorySize, SMEM);

    // prep
    transpose_half<<<dim3(CC/32, CC/32), dim3(32,8)>>>(Wa1, wt1, CC, CC);
    transpose_half<<<dim3(CC/32, HH/32), dim3(32,8)>>>(Wa2, wt2, CC, HH);
    prod_kernel<<<M, 256>>>(x, p);

    // h1 = relu(p @ Wa1 + ba1)   [half out]
    hgemm<1><<<dim3(CC/256, MT), 256, SMEM>>>(p, wt1, ba1, h1, nullptr, nullptr, M, CC, CC);
    // s partials (h2 never materialized)
    hgemm<2><<<dim3(HH/256, MT), 256, SMEM>>>(h1, wt2, ba2, nullptr, Wa3, spart, M, CC, HH);

    agg_kernel<<<MR, 256>>>(x, spart, ba3, (const float*)d_in[1], (const float*)d_in[2], at, mt);

    const int MRT = (MR + 127) / 128; // 6
    // layer-1 pair merged via blockIdx.z
    mma_gemm<<<dim3(CC/128, MRT, 2), 256>>>(
        at, mt, (const float*)d_in[9], (const float*)d_in[13],
        (const float*)d_in[10], (const float*)d_in[14],
        t1a, t1m, nullptr, MR, CC, CC, 0);
    // layer-2 (serial: RMW on out)
    mma_gemm<<<dim3(CC/128, MRT, 1), 256>>>(
        t1a, nullptr, (const float*)d_in[11], nullptr,
        (const float*)d_in[12], nullptr,
        out, nullptr, x, MR, CC, CC, 1);
    mma_gemm<<<dim3(CC/128, MRT, 1), 256>>>(
        t1m, nullptr, (const float*)d_in[15], nullptr,
        (const float*)d_in[16], nullptr,
        out, nullptr, out, MR, CC, CC, 2);
}